// round 4
// baseline (speedup 1.0000x reference)
#include <cuda_runtime.h>
#include <cuda_bf16.h>
#include <cstdint>

#define NN 25000
#define EE 400000

typedef unsigned long long ull;

// ---- scratch (static device globals; no allocation) ----
__device__ float g_node_score[NN];
__device__ int   g_segmax[NN];
__device__ float g_se[NN];
__device__ float g_agg[(size_t)NN * 128];
__device__ float g_scores[EE];
__device__ float g_ex[EE];

// ---- helpers ----
__device__ __forceinline__ ull pk(float lo, float hi) {
    ull r; asm("mov.b64 %0, {%1,%2};" : "=l"(r) : "f"(lo), "f"(hi)); return r;
}
__device__ __forceinline__ float2 upk(ull v) {
    float2 r; asm("mov.b64 {%0,%1}, %2;" : "=f"(r.x), "=f"(r.y) : "l"(v)); return r;
}
__device__ __forceinline__ void fma2(ull& d, ull a, ull b) {
    asm("fma.rn.f32x2 %0, %1, %2, %0;" : "+l"(d) : "l"(a), "l"(b));
}
__device__ __forceinline__ float wred(float v) {
#pragma unroll
    for (int o = 16; o; o >>= 1) v += __shfl_xor_sync(0xffffffffu, v, o);
    return v;
}
__device__ __forceinline__ int f2o(float f) { int i = __float_as_int(f); return i >= 0 ? i : i ^ 0x7fffffff; }
__device__ __forceinline__ float o2f(int i) { return __int_as_float(i >= 0 ? i : i ^ 0x7fffffff); }

// Generic smem-A (fully resident) x global-B GEMM microkernel.
// Block tile: 64 rows x NCOLS cols, 256 threads, each thread 4 rows x (NCOLS/16) cols
// as f32x2 pairs. B streamed in 16-row tiles through Bs.
template <int KDIM, int NCOLS>
__device__ __forceinline__ void gemm_smem(const float* Xs, int ldx,
                                          const float* __restrict__ Bg,
                                          float* Bs, ull* acc, int tid) {
    constexpr int NP = NCOLS / 32;
    const int tx = tid & 15, ty = tid >> 4;
#pragma unroll 1
    for (int k0 = 0; k0 < KDIM; k0 += 16) {
        __syncthreads();
        constexpr int NF4 = 16 * NCOLS / 4;
#pragma unroll
        for (int j = 0; j < NF4 / 256; j++) {
            int f = tid + j * 256;
            int r = f / (NCOLS / 4);
            int c = (f - r * (NCOLS / 4)) * 4;
            *(float4*)(Bs + r * NCOLS + c) = *(const float4*)(Bg + (size_t)(k0 + r) * NCOLS + c);
        }
        __syncthreads();
#pragma unroll
        for (int kk = 0; kk < 16; kk++) {
            ull aa[4];
#pragma unroll
            for (int i = 0; i < 4; i++) { float a = Xs[(ty * 4 + i) * ldx + k0 + kk]; aa[i] = pk(a, a); }
#pragma unroll
            for (int p = 0; p < NP; p++) {
                ull bb = *(const ull*)(Bs + kk * NCOLS + (tx + 16 * p) * 2);
#pragma unroll
                for (int i = 0; i < 4; i++) fma2(acc[i * NP + p], aa[i], bb);
            }
        }
    }
    __syncthreads();
}

// ---------------- K0: per-node attention-score part + scratch init ----------------
__global__ void k0_node_prep(const float* __restrict__ nf, const float* __restrict__ aw) {
    int node = blockIdx.x * 8 + (threadIdx.x >> 5);
    int lane = threadIdx.x & 31;
    if (node >= NN) return;
    const float* row = nf + (size_t)node * 256;
    float s = 0.f;
#pragma unroll
    for (int c = lane; c < 256; c += 32) {
        const float4 a = *(const float4*)(aw + c * 4);
        s += row[c] * (a.x + a.y + a.z + a.w);
    }
    s = wred(s);
    if (lane == 0) {
        g_node_score[node] = s * 0.25f;
        g_segmax[node] = (int)0x80000000;
        g_se[node] = 0.f;
    }
    float* ag = g_agg + (size_t)node * 128;
    for (int c = lane; c < 128; c += 32) ag[c] = 0.f;
}

// ---------------- K1: fused edge MLP + residual + LN + score + segmax ----------------
// 64 edges per block; phase1: gathered A(64x640) @ ew1(640x256) relu;
// phase2: hidden @ ew2(256x128); epilogue: +eb2 +edge residual, LN, e out, score.
__global__ __launch_bounds__(256, 2) void k1_edge(
    const float* __restrict__ nf, const float* __restrict__ ef, const int* __restrict__ ei,
    const float* __restrict__ ew1, const float* __restrict__ eb1,
    const float* __restrict__ ew2, const float* __restrict__ eb2,
    const float* __restrict__ eng, const float* __restrict__ enb,
    const float* __restrict__ aw, const float* __restrict__ ab,
    float* __restrict__ e_out) {
    extern __shared__ float sm[];
    float* X  = sm;              // 64*256
    float* Bs = X + 64 * 256;    // 16*256
    float* As = Bs + 16 * 256;   // 64*17
    int* sidx = (int*)(As + 64 * 17);
    int* didx = sidx + 64;
    const int tid = threadIdx.x;
    const int tx = tid & 15, ty = tid >> 4;
    const int e0 = blockIdx.x * 64;
    if (tid < 64) sidx[tid] = ei[e0 + tid];
    else if (tid < 128) didx[tid - 64] = ei[EE + e0 + tid - 64];

    ull acc[4][8];
#pragma unroll
    for (int i = 0; i < 4; i++)
#pragma unroll
        for (int p = 0; p < 8; p++) acc[i][p] = 0ull;

    const int m  = tid >> 2;
    const int kl = (tid & 3) * 4;
#pragma unroll 1
    for (int k0 = 0; k0 < 640; k0 += 16) {
        __syncthreads();
        // gather A tile (src-node / dst-node / edge feature regions)
        int kg = k0 + kl;
        float4 v;
        if (kg < 256)      v = *(const float4*)(nf + (size_t)sidx[m] * 256 + kg);
        else if (kg < 512) v = *(const float4*)(nf + (size_t)didx[m] * 256 + (kg - 256));
        else               v = *(const float4*)(ef + (size_t)(e0 + m) * 128 + (kg - 512));
        As[m * 17 + kl + 0] = v.x; As[m * 17 + kl + 1] = v.y;
        As[m * 17 + kl + 2] = v.z; As[m * 17 + kl + 3] = v.w;
        // B tile of ew1
#pragma unroll
        for (int j = 0; j < 4; j++) {
            int f = tid + j * 256;
            int r = f >> 6;
            int c = (f & 63) * 4;
            *(float4*)(Bs + r * 256 + c) = *(const float4*)(ew1 + (size_t)(k0 + r) * 256 + c);
        }
        __syncthreads();
#pragma unroll
        for (int kk = 0; kk < 16; kk++) {
            ull aa[4];
#pragma unroll
            for (int i = 0; i < 4; i++) { float a = As[(ty * 4 + i) * 17 + kk]; aa[i] = pk(a, a); }
#pragma unroll
            for (int p = 0; p < 8; p++) {
                ull bb = *(const ull*)(Bs + kk * 256 + (tx + 16 * p) * 2);
#pragma unroll
                for (int i = 0; i < 4; i++) fma2(acc[i][p], aa[i], bb);
            }
        }
    }
    __syncthreads();
    // hidden = relu(acc + eb1) -> X (ld 256)
#pragma unroll
    for (int i = 0; i < 4; i++) {
        int r = ty * 4 + i;
#pragma unroll
        for (int p = 0; p < 8; p++) {
            int c0 = (tx + 16 * p) * 2;
            float2 v = upk(acc[i][p]);
            v.x = fmaxf(v.x + eb1[c0], 0.f);
            v.y = fmaxf(v.y + eb1[c0 + 1], 0.f);
            *(float2*)(X + r * 256 + c0) = v;
        }
    }
    // phase 2: hidden(64x256) @ ew2(256x128)
    ull acc2[16];
#pragma unroll
    for (int i = 0; i < 16; i++) acc2[i] = 0ull;
    gemm_smem<256, 128>(X, 256, ew2, Bs, acc2, tid);
    // upd + eb2 + edge residual -> X (ld 128)
#pragma unroll
    for (int i = 0; i < 4; i++) {
        int r = ty * 4 + i; size_t row = (size_t)e0 + r;
#pragma unroll
        for (int p = 0; p < 4; p++) {
            int c0 = (tx + 16 * p) * 2;
            float2 v = upk(acc2[i * 4 + p]);
            v.x += eb2[c0]     + ef[row * 128 + c0];
            v.y += eb2[c0 + 1] + ef[row * 128 + c0 + 1];
            *(float2*)(X + r * 128 + c0) = v;
        }
    }
    __syncthreads();
    // LN over 128 + e output + fused attention score + segment max
    const int w = tid >> 5, lane = tid & 31;
    const float abm = 0.25f * (ab[0] + ab[1] + ab[2] + ab[3]);
    const int c = lane * 4;
    float4 g4 = *(const float4*)(eng + c);
    float4 b4 = *(const float4*)(enb + c);
    float4 a0 = *(const float4*)(aw + (256 + c) * 4);
    float4 a1 = *(const float4*)(aw + (256 + c + 1) * 4);
    float4 a2 = *(const float4*)(aw + (256 + c + 2) * 4);
    float4 a3 = *(const float4*)(aw + (256 + c + 3) * 4);
    float wa0 = a0.x + a0.y + a0.z + a0.w;
    float wa1 = a1.x + a1.y + a1.z + a1.w;
    float wa2 = a2.x + a2.y + a2.z + a2.w;
    float wa3 = a3.x + a3.y + a3.z + a3.w;
#pragma unroll 1
    for (int rr = 0; rr < 8; rr++) {
        int r = w * 8 + rr;
        float4 v = *(const float4*)(X + r * 128 + c);
        float mean = wred(v.x + v.y + v.z + v.w) * (1.f / 128.f);
        float dx = v.x - mean, dy = v.y - mean, dz = v.z - mean, dw = v.w - mean;
        float var = wred(dx * dx + dy * dy + dz * dz + dw * dw) * (1.f / 128.f);
        float rstd = rsqrtf(var + 1e-5f);
        float4 y;
        y.x = dx * rstd * g4.x + b4.x;
        y.y = dy * rstd * g4.y + b4.y;
        y.z = dz * rstd * g4.z + b4.z;
        y.w = dw * rstd * g4.w + b4.w;
        size_t row = (size_t)e0 + r;
        *(float4*)(e_out + row * 128 + c) = y;
        float sp = wred(y.x * wa0 + y.y * wa1 + y.z * wa2 + y.w * wa3);
        if (lane == 0) {
            int d = didx[r];
            float sc = sp * 0.25f + g_node_score[d] + abm;
            g_scores[row] = sc;
            atomicMax(&g_segmax[d], f2o(sc));
        }
    }
}

// ---------------- K2: ex = exp(score - segmax[dst]); se[dst] += ex ----------------
__global__ void k2_exp(const int* __restrict__ ei) {
    int e = blockIdx.x * 256 + threadIdx.x;
    if (e >= EE) return;
    int d = ei[EE + e];
    float ex = expf(g_scores[e] - o2f(g_segmax[d]));
    g_ex[e] = ex;
    atomicAdd(&g_se[d], ex);
}

// ---------------- K3: agg[dst] += w_e * e_e ----------------
__global__ void k3_scatter(const int* __restrict__ ei, const float* __restrict__ e_feat) {
    int e = blockIdx.x * 2 + (threadIdx.x >> 7);
    int c = threadIdx.x & 127;
    int d = ei[EE + e];
    float w = g_ex[e] / (g_se[d] + 1e-6f);
    atomicAdd(&g_agg[(size_t)d * 128 + c], w * e_feat[(size_t)e * 128 + c]);
}

// ---------------- K4: node update (3 fused GEMMs + residual + LN) ----------------
__global__ __launch_bounds__(256, 2) void k4_node(
    const float* __restrict__ nf,
    const float* __restrict__ evw, const float* __restrict__ evb,
    const float* __restrict__ ow1, const float* __restrict__ ob1,
    const float* __restrict__ ow2, const float* __restrict__ ob2,
    const float* __restrict__ nng, const float* __restrict__ nnb,
    float* __restrict__ n_out) {
    extern __shared__ float sm[];
    float* X  = sm;              // 64*256
    float* Bs = X + 64 * 256;    // 16*256
    float* sw = Bs + 16 * 256;   // 64
    const int tid = threadIdx.x;
    const int tx = tid & 15, ty = tid >> 4;
    const int n0 = blockIdx.x * 64;
    // load agg tile (ld 128) + sumw
#pragma unroll
    for (int j = 0; j < 8; j++) {
        int f = tid + j * 256;
        int r = f >> 5; int c = (f & 31) * 4;
        float4 v = make_float4(0.f, 0.f, 0.f, 0.f);
        if (n0 + r < NN) v = *(const float4*)(g_agg + (size_t)(n0 + r) * 128 + c);
        *(float4*)(X + r * 128 + c) = v;
    }
    if (tid < 64) {
        int nn2 = n0 + tid;
        float se = (nn2 < NN) ? g_se[nn2] : 0.f;
        sw[tid] = se / (se + 1e-6f);
    }
    ull acc[32];
#pragma unroll
    for (int i = 0; i < 32; i++) acc[i] = 0ull;
    // messages = agg @ evw + sumw*evb
    gemm_smem<128, 256>(X, 128, evw, Bs, acc, tid);
#pragma unroll
    for (int i = 0; i < 4; i++) {
        int r = ty * 4 + i;
        float s = sw[r];
#pragma unroll
        for (int p = 0; p < 8; p++) {
            int c0 = (tx + 16 * p) * 2;
            float2 v = upk(acc[i * 8 + p]);
            v.x += s * evb[c0];
            v.y += s * evb[c0 + 1];
            *(float2*)(X + r * 256 + c0) = v;
        }
    }
    // h = relu(messages @ ow1 + ob1)
#pragma unroll
    for (int i = 0; i < 32; i++) acc[i] = 0ull;
    gemm_smem<256, 256>(X, 256, ow1, Bs, acc, tid);
#pragma unroll
    for (int i = 0; i < 4; i++) {
        int r = ty * 4 + i;
#pragma unroll
        for (int p = 0; p < 8; p++) {
            int c0 = (tx + 16 * p) * 2;
            float2 v = upk(acc[i * 8 + p]);
            v.x = fmaxf(v.x + ob1[c0], 0.f);
            v.y = fmaxf(v.y + ob1[c0 + 1], 0.f);
            *(float2*)(X + r * 256 + c0) = v;
        }
    }
    // out = h @ ow2 + ob2 + node residual
#pragma unroll
    for (int i = 0; i < 32; i++) acc[i] = 0ull;
    gemm_smem<256, 256>(X, 256, ow2, Bs, acc, tid);
#pragma unroll
    for (int i = 0; i < 4; i++) {
        int r = ty * 4 + i;
        int row = n0 + r;
#pragma unroll
        for (int p = 0; p < 8; p++) {
            int c0 = (tx + 16 * p) * 2;
            float2 v = upk(acc[i * 8 + p]);
            v.x += ob2[c0];
            v.y += ob2[c0 + 1];
            if (row < NN) {
                v.x += nf[(size_t)row * 256 + c0];
                v.y += nf[(size_t)row * 256 + c0 + 1];
            }
            *(float2*)(X + r * 256 + c0) = v;
        }
    }
    __syncthreads();
    // LN over 256
    const int wp = tid >> 5, lane = tid & 31;
    const int cb = lane * 8;
    float4 g0 = *(const float4*)(nng + cb), g1 = *(const float4*)(nng + cb + 4);
    float4 h0 = *(const float4*)(nnb + cb), h1 = *(const float4*)(nnb + cb + 4);
#pragma unroll 1
    for (int rr = 0; rr < 8; rr++) {
        int r = wp * 8 + rr;
        int row = n0 + r;
        float4 v0 = *(const float4*)(X + r * 256 + cb);
        float4 v1 = *(const float4*)(X + r * 256 + cb + 4);
        float mean = wred(v0.x + v0.y + v0.z + v0.w + v1.x + v1.y + v1.z + v1.w) * (1.f / 256.f);
        float d0x = v0.x - mean, d0y = v0.y - mean, d0z = v0.z - mean, d0w = v0.w - mean;
        float d1x = v1.x - mean, d1y = v1.y - mean, d1z = v1.z - mean, d1w = v1.w - mean;
        float var = wred(d0x * d0x + d0y * d0y + d0z * d0z + d0w * d0w +
                         d1x * d1x + d1y * d1y + d1z * d1z + d1w * d1w) * (1.f / 256.f);
        float rstd = rsqrtf(var + 1e-5f);
        if (row < NN) {
            float4 y0, y1;
            y0.x = d0x * rstd * g0.x + h0.x; y0.y = d0y * rstd * g0.y + h0.y;
            y0.z = d0z * rstd * g0.z + h0.z; y0.w = d0w * rstd * g0.w + h0.w;
            y1.x = d1x * rstd * g1.x + h1.x; y1.y = d1y * rstd * g1.y + h1.y;
            y1.z = d1z * rstd * g1.z + h1.z; y1.w = d1w * rstd * g1.w + h1.w;
            *(float4*)(n_out + (size_t)row * 256 + cb) = y0;
            *(float4*)(n_out + (size_t)row * 256 + cb + 4) = y1;
        }
    }
}

// ---------------- launch ----------------
extern "C" void kernel_launch(void* const* d_in, const int* in_sizes, int n_in,
                              void* d_out, int out_size) {
    const float* nf  = (const float*)d_in[0];
    const float* ef  = (const float*)d_in[1];
    const int*   ei  = (const int*)d_in[2];
    const float* ew1 = (const float*)d_in[3];
    const float* eb1 = (const float*)d_in[4];
    const float* ew2 = (const float*)d_in[5];
    const float* eb2 = (const float*)d_in[6];
    const float* eng = (const float*)d_in[7];
    const float* enb = (const float*)d_in[8];
    const float* aw  = (const float*)d_in[9];
    const float* ab  = (const float*)d_in[10];
    const float* evw = (const float*)d_in[11];
    const float* evb = (const float*)d_in[12];
    const float* ow1 = (const float*)d_in[13];
    const float* ob1 = (const float*)d_in[14];
    const float* ow2 = (const float*)d_in[15];
    const float* ob2 = (const float*)d_in[16];
    const float* nng = (const float*)d_in[17];
    const float* nnb = (const float*)d_in[18];

    float* out = (float*)d_out;
    float* n_out = out;                        // (N, 256)
    float* e_out = out + (size_t)NN * 256;     // (E, 128)

    const int SMEM1 = (64 * 256 + 16 * 256 + 64 * 17) * 4 + 128 * 4;  // 86784 B
    const int SMEM4 = (64 * 256 + 16 * 256 + 64) * 4;                 // 82176 B
    cudaFuncSetAttribute(k1_edge, cudaFuncAttributeMaxDynamicSharedMemorySize, SMEM1);
    cudaFuncSetAttribute(k4_node, cudaFuncAttributeMaxDynamicSharedMemorySize, SMEM4);

    k0_node_prep<<<(NN + 7) / 8, 256>>>(nf, aw);
    k1_edge<<<EE / 64, 256, SMEM1>>>(nf, ef, ei, ew1, eb1, ew2, eb2, eng, enb, aw, ab, e_out);
    k2_exp<<<(EE + 255) / 256, 256>>>(ei);
    k3_scatter<<<EE / 2, 256>>>(ei, e_out);
    k4_node<<<(NN + 63) / 64, 256, SMEM4>>>(nf, evw, evb, ow1, ob1, ow2, ob2, nng, nnb, n_out);
}

// round 9
// speedup vs baseline: 1.0846x; 1.0846x over previous
#include <cuda_runtime.h>
#include <cuda_bf16.h>
#include <cstdint>

#define NN 25000
#define EE 400000
#define TILES (EE / 128)   // 3125

typedef unsigned long long ull;

// ---- scratch (static device globals; no allocation) ----
__device__ float g_node_score[NN];
__device__ int   g_segmax[NN];
__device__ float g_se[NN];
__device__ float g_agg[(size_t)NN * 128];
__device__ float g_scores[EE];
__device__ float g_ex[EE];
// pre-split / transposed weights (bf16 hi/lo), K-major [N][K]
__device__ __nv_bfloat16 g_w1t_hi[256 * 640];
__device__ __nv_bfloat16 g_w1t_lo[256 * 640];
__device__ __nv_bfloat16 g_w2t_hi[128 * 256];
__device__ __nv_bfloat16 g_w2t_lo[128 * 256];

// ---- generic helpers ----
__device__ __forceinline__ ull pk(float lo, float hi) {
    ull r; asm("mov.b64 %0, {%1,%2};" : "=l"(r) : "f"(lo), "f"(hi)); return r;
}
__device__ __forceinline__ float2 upk(ull v) {
    float2 r; asm("mov.b64 {%0,%1}, %2;" : "=f"(r.x), "=f"(r.y) : "l"(v)); return r;
}
__device__ __forceinline__ void fma2(ull& d, ull a, ull b) {
    asm("fma.rn.f32x2 %0, %1, %2, %0;" : "+l"(d) : "l"(a), "l"(b));
}
__device__ __forceinline__ float wred(float v) {
#pragma unroll
    for (int o = 16; o; o >>= 1) v += __shfl_xor_sync(0xffffffffu, v, o);
    return v;
}
__device__ __forceinline__ int f2o(float f) { int i = __float_as_int(f); return i >= 0 ? i : i ^ 0x7fffffff; }
__device__ __forceinline__ float o2f(int i) { return __int_as_float(i >= 0 ? i : i ^ 0x7fffffff); }

// pack (lo -> lower 16, hi -> upper 16) as bf16x2
__device__ __forceinline__ uint32_t bfpair(float lo, float hi) {
    uint32_t u; asm("cvt.rn.bf16x2.f32 %0, %1, %2;" : "=r"(u) : "f"(hi), "f"(lo)); return u;
}
__device__ __forceinline__ float bflo(uint32_t u) { return __uint_as_float(u << 16); }
__device__ __forceinline__ float bfhi(uint32_t u) { return __uint_as_float(u & 0xffff0000u); }

__device__ __forceinline__ void split8(float4 a, float4 b, uint4& hv, uint4& lv) {
    uint32_t u0 = bfpair(a.x, a.y);
    uint32_t u1 = bfpair(a.z, a.w);
    uint32_t u2 = bfpair(b.x, b.y);
    uint32_t u3 = bfpair(b.z, b.w);
    uint32_t l0 = bfpair(a.x - bflo(u0), a.y - bfhi(u0));
    uint32_t l1 = bfpair(a.z - bflo(u1), a.w - bfhi(u1));
    uint32_t l2 = bfpair(b.x - bflo(u2), b.y - bfhi(u2));
    uint32_t l3 = bfpair(b.z - bflo(u3), b.w - bfhi(u3));
    hv = make_uint4(u0, u1, u2, u3);
    lv = make_uint4(l0, l1, l2, l3);
}

// warp-level bf16 MMA (sm_80+ baseline PTX; valid on plain sm_100 target)
__device__ __forceinline__ void mma16816(float* d, const uint32_t* a, uint32_t b0, uint32_t b1) {
    asm volatile(
        "mma.sync.aligned.m16n8k16.row.col.f32.bf16.bf16.f32 "
        "{%0,%1,%2,%3}, {%4,%5,%6,%7}, {%8,%9}, {%0,%1,%2,%3};"
        : "+f"(d[0]), "+f"(d[1]), "+f"(d[2]), "+f"(d[3])
        : "r"(a[0]), "r"(a[1]), "r"(a[2]), "r"(a[3]), "r"(b0), "r"(b1));
}

// ---------------- prep: transpose + bf16-split weights ----------------
__global__ void k_prep(const float* __restrict__ ew1, const float* __restrict__ ew2) {
    int i = blockIdx.x * 256 + threadIdx.x;
    if (i < 256 * 640) {
        int n = i / 640, k = i - n * 640;
        float x = ew1[(size_t)k * 256 + n];
        __nv_bfloat16 h = __float2bfloat16(x);
        g_w1t_hi[i] = h;
        g_w1t_lo[i] = __float2bfloat16(x - __bfloat162float(h));
    } else {
        int j = i - 256 * 640;
        if (j < 128 * 256) {
            int n = j / 256, k = j - n * 256;
            float x = ew2[(size_t)k * 128 + n];
            __nv_bfloat16 h = __float2bfloat16(x);
            g_w2t_hi[j] = h;
            g_w2t_lo[j] = __float2bfloat16(x - __bfloat162float(h));
        }
    }
}

// ---------------- K0: per-node attention-score part + scratch init ----------------
__global__ void k0_node_prep(const float* __restrict__ nf, const float* __restrict__ aw) {
    int node = blockIdx.x * 8 + (threadIdx.x >> 5);
    int lane = threadIdx.x & 31;
    if (node >= NN) return;
    const float* row = nf + (size_t)node * 256;
    float s = 0.f;
#pragma unroll
    for (int c = lane; c < 256; c += 32) {
        const float4 a = *(const float4*)(aw + c * 4);
        s += row[c] * (a.x + a.y + a.z + a.w);
    }
    s = wred(s);
    if (lane == 0) {
        g_node_score[node] = s * 0.25f;
        g_segmax[node] = (int)0x80000000;
        g_se[node] = 0.f;
    }
    float* ag = g_agg + (size_t)node * 128;
    for (int c = lane; c < 128; c += 32) ag[c] = 0.f;
}

// ---------------- K1: warp-MMA bf16-split fused edge MLP ----------------
// SMEM layout (bytes), rows padded to 72 bf16 (144B = 9 x 16B granules, conflict-free):
//  0:     sidx[128] | 512: didx[128]
//  1024:  A chunk hi [128][72]  (18432)     (also X fp32 [128][132] = 67584 in epilogue2)
//  19456: A chunk lo            (18432)
//  37888: B chunk hi            (18432)
//  56320: B chunk lo            (18432)
//  74752: H chunks: 4 x (hi 18432 + lo 18432) = 147456  -> total 222208
#define OFF_AH 1024
#define OFF_AL 19456
#define OFF_BH 37888
#define OFF_BL 56320
#define OFF_H  74752
#define OFF_X  1024
#define SMEM_K1 222208

__global__ __launch_bounds__(256, 1) void k1_edge_mma(
    const float* __restrict__ nf, const float* __restrict__ ef, const int* __restrict__ ei,
    const float* __restrict__ eb1, const float* __restrict__ eb2,
    const float* __restrict__ eng, const float* __restrict__ enb,
    const float* __restrict__ aw, const float* __restrict__ ab,
    float* __restrict__ e_out) {
    extern __shared__ char smb[];
    int* sidx = (int*)smb;
    int* didx = (int*)(smb + 512);
    const int tid = threadIdx.x;
    const int wid = tid >> 5, lane = tid & 31;
    const int wm = wid >> 1, wn = wid & 1;
    const int m0 = wm * 32;
    const int qr = lane >> 2;         // 0..7
    const int qc = (lane & 3) * 2;    // 0,2,4,6
    const int e0 = blockIdx.x * 128;

    if (tid < 128) sidx[tid] = ei[e0 + tid];
    else didx[tid - 128] = ei[EE + e0 + tid - 128];

    float acc[2][8][4];

    // ================= phase 1: two N-halves of C(128x256) =================
#pragma unroll 1
    for (int h = 0; h < 2; h++) {
#pragma unroll
        for (int mt = 0; mt < 2; mt++)
#pragma unroll
            for (int nt = 0; nt < 8; nt++)
#pragma unroll
                for (int q = 0; q < 4; q++) acc[mt][nt][q] = 0.f;

#pragma unroll 1
        for (int c = 0; c < 10; c++) {
            __syncthreads();
            // producer: gather + split A chunk (128 rows x 64 k)
            {
                const int row = tid >> 1, ch = (tid & 1) * 32;
                const int kg = c * 64;
                const float* base;
                if (kg < 256)      base = nf + (size_t)sidx[row] * 256 + kg;
                else if (kg < 512) base = nf + (size_t)didx[row] * 256 + (kg - 256);
                else               base = ef + (size_t)(e0 + row) * 128 + (kg - 512);
#pragma unroll
                for (int g = 0; g < 4; g++) {
                    float4 a = *(const float4*)(base + ch + g * 8);
                    float4 b = *(const float4*)(base + ch + g * 8 + 4);
                    uint4 hv, lv; split8(a, b, hv, lv);
                    uint32_t off = (uint32_t)(row * 144 + (ch + g * 8) * 2);
                    *(uint4*)(smb + OFF_AH + off) = hv;
                    *(uint4*)(smb + OFF_AL + off) = lv;
                }
            }
            // producer: W1 chunk (128 n-rows of this half x 64 k), pre-split
            {
                const int nrow = tid & 127;
                const __nv_bfloat16* src =
                    (tid < 128 ? g_w1t_hi : g_w1t_lo) + (size_t)(h * 128 + nrow) * 640 + c * 64;
                char* dst = smb + (tid < 128 ? OFF_BH : OFF_BL) + nrow * 144;
#pragma unroll
                for (int g = 0; g < 8; g++)
                    *(uint4*)(dst + g * 16) = *(const uint4*)(src + g * 8);
            }
            __syncthreads();
            // consumer: mma over 4 k16 steps
#pragma unroll
            for (int ks = 0; ks < 4; ks++) {
                const int kb = ks * 16;
                uint32_t Ah[2][4], Al[2][4];
#pragma unroll
                for (int mt = 0; mt < 2; mt++) {
                    const int r0 = m0 + mt * 16 + qr;
                    Ah[mt][0] = *(const uint32_t*)(smb + OFF_AH + r0 * 144 + (kb + qc) * 2);
                    Ah[mt][1] = *(const uint32_t*)(smb + OFF_AH + (r0 + 8) * 144 + (kb + qc) * 2);
                    Ah[mt][2] = *(const uint32_t*)(smb + OFF_AH + r0 * 144 + (kb + 8 + qc) * 2);
                    Ah[mt][3] = *(const uint32_t*)(smb + OFF_AH + (r0 + 8) * 144 + (kb + 8 + qc) * 2);
                    Al[mt][0] = *(const uint32_t*)(smb + OFF_AL + r0 * 144 + (kb + qc) * 2);
                    Al[mt][1] = *(const uint32_t*)(smb + OFF_AL + (r0 + 8) * 144 + (kb + qc) * 2);
                    Al[mt][2] = *(const uint32_t*)(smb + OFF_AL + r0 * 144 + (kb + 8 + qc) * 2);
                    Al[mt][3] = *(const uint32_t*)(smb + OFF_AL + (r0 + 8) * 144 + (kb + 8 + qc) * 2);
                }
#pragma unroll
                for (int nt = 0; nt < 8; nt++) {
                    const int nr = wn * 64 + nt * 8 + qr;
                    uint32_t bh0 = *(const uint32_t*)(smb + OFF_BH + nr * 144 + (kb + qc) * 2);
                    uint32_t bh1 = *(const uint32_t*)(smb + OFF_BH + nr * 144 + (kb + 8 + qc) * 2);
                    uint32_t bl0 = *(const uint32_t*)(smb + OFF_BL + nr * 144 + (kb + qc) * 2);
                    uint32_t bl1 = *(const uint32_t*)(smb + OFF_BL + nr * 144 + (kb + 8 + qc) * 2);
                    mma16816(acc[0][nt], Ah[0], bh0, bh1);
                    mma16816(acc[1][nt], Ah[1], bh0, bh1);
                    mma16816(acc[0][nt], Ah[0], bl0, bl1);
                    mma16816(acc[1][nt], Ah[1], bl0, bl1);
                    mma16816(acc[0][nt], Al[0], bh0, bh1);
                    mma16816(acc[1][nt], Al[1], bh0, bh1);
                }
            }
        }
        // epilogue 1: bias + relu + bf16-split -> H chunk (h*2 + wn)
        {
            char* Hh = smb + OFF_H + (h * 2 + wn) * 36864;
            char* Hl = Hh + 18432;
#pragma unroll
            for (int mt = 0; mt < 2; mt++)
#pragma unroll
                for (int nt = 0; nt < 8; nt++) {
                    const int gcol = h * 128 + wn * 64 + nt * 8 + qc;
                    const float b0v = eb1[gcol], b1v = eb1[gcol + 1];
                    const int row = m0 + mt * 16 + qr;
                    const int colc = nt * 8 + qc;
                    float f0 = fmaxf(acc[mt][nt][0] + b0v, 0.f);
                    float f1 = fmaxf(acc[mt][nt][1] + b1v, 0.f);
                    uint32_t uh = bfpair(f0, f1);
                    *(uint32_t*)(Hh + row * 144 + colc * 2) = uh;
                    *(uint32_t*)(Hl + row * 144 + colc * 2) = bfpair(f0 - bflo(uh), f1 - bfhi(uh));
                    float f2 = fmaxf(acc[mt][nt][2] + b0v, 0.f);
                    float f3 = fmaxf(acc[mt][nt][3] + b1v, 0.f);
                    uint32_t uh2 = bfpair(f2, f3);
                    *(uint32_t*)(Hh + (row + 8) * 144 + colc * 2) = uh2;
                    *(uint32_t*)(Hl + (row + 8) * 144 + colc * 2) = bfpair(f2 - bflo(uh2), f3 - bfhi(uh2));
                }
        }
    }

    // ================= phase 2: H(128x256) @ W2(256x128) =================
#pragma unroll
    for (int mt = 0; mt < 2; mt++)
#pragma unroll
        for (int nt = 0; nt < 8; nt++)
#pragma unroll
            for (int q = 0; q < 4; q++) acc[mt][nt][q] = 0.f;

#pragma unroll 1
    for (int c2 = 0; c2 < 4; c2++) {
        __syncthreads();
        {
            const int nrow = tid & 127;
            const __nv_bfloat16* src =
                (tid < 128 ? g_w2t_hi : g_w2t_lo) + (size_t)nrow * 256 + c2 * 64;
            char* dst = smb + (tid < 128 ? OFF_BH : OFF_BL) + nrow * 144;
#pragma unroll
            for (int g = 0; g < 8; g++)
                *(uint4*)(dst + g * 16) = *(const uint4*)(src + g * 8);
        }
        __syncthreads();
        char* HhB = smb + OFF_H + c2 * 36864;
        char* HlB = HhB + 18432;
#pragma unroll
        for (int ks = 0; ks < 4; ks++) {
            const int kb = ks * 16;
            uint32_t Ah[2][4], Al[2][4];
#pragma unroll
            for (int mt = 0; mt < 2; mt++) {
                const int r0 = m0 + mt * 16 + qr;
                Ah[mt][0] = *(const uint32_t*)(HhB + r0 * 144 + (kb + qc) * 2);
                Ah[mt][1] = *(const uint32_t*)(HhB + (r0 + 8) * 144 + (kb + qc) * 2);
                Ah[mt][2] = *(const uint32_t*)(HhB + r0 * 144 + (kb + 8 + qc) * 2);
                Ah[mt][3] = *(const uint32_t*)(HhB + (r0 + 8) * 144 + (kb + 8 + qc) * 2);
                Al[mt][0] = *(const uint32_t*)(HlB + r0 * 144 + (kb + qc) * 2);
                Al[mt][1] = *(const uint32_t*)(HlB + (r0 + 8) * 144 + (kb + qc) * 2);
                Al[mt][2] = *(const uint32_t*)(HlB + r0 * 144 + (kb + 8 + qc) * 2);
                Al[mt][3] = *(const uint32_t*)(HlB + (r0 + 8) * 144 + (kb + 8 + qc) * 2);
            }
#pragma unroll
            for (int nt = 0; nt < 8; nt++) {
                const int nr = wn * 64 + nt * 8 + qr;
                uint32_t bh0 = *(const uint32_t*)(smb + OFF_BH + nr * 144 + (kb + qc) * 2);
                uint32_t bh1 = *(const uint32_t*)(smb + OFF_BH + nr * 144 + (kb + 8 + qc) * 2);
                uint32_t bl0 = *(const uint32_t*)(smb + OFF_BL + nr * 144 + (kb + qc) * 2);
                uint32_t bl1 = *(const uint32_t*)(smb + OFF_BL + nr * 144 + (kb + 8 + qc) * 2);
                mma16816(acc[0][nt], Ah[0], bh0, bh1);
                mma16816(acc[1][nt], Ah[1], bh0, bh1);
                mma16816(acc[0][nt], Ah[0], bl0, bl1);
                mma16816(acc[1][nt], Ah[1], bl0, bl1);
                mma16816(acc[0][nt], Al[0], bh0, bh1);
                mma16816(acc[1][nt], Al[1], bh0, bh1);
            }
        }
    }

    // ================= epilogue 2: bias + residual -> X, LN, score =================
    __syncthreads();
    float* X = (float*)(smb + OFF_X);
#pragma unroll
    for (int mt = 0; mt < 2; mt++)
#pragma unroll
        for (int nt = 0; nt < 8; nt++) {
            const int col = wn * 64 + nt * 8 + qc;
            const float b0v = eb2[col], b1v = eb2[col + 1];
            const int row = m0 + mt * 16 + qr;
            float2 v0, v1;
            v0.x = acc[mt][nt][0] + b0v + ef[(size_t)(e0 + row) * 128 + col];
            v0.y = acc[mt][nt][1] + b1v + ef[(size_t)(e0 + row) * 128 + col + 1];
            v1.x = acc[mt][nt][2] + b0v + ef[(size_t)(e0 + row + 8) * 128 + col];
            v1.y = acc[mt][nt][3] + b1v + ef[(size_t)(e0 + row + 8) * 128 + col + 1];
            *(float2*)(X + row * 132 + col) = v0;
            *(float2*)(X + (row + 8) * 132 + col) = v1;
        }
    __syncthreads();

    const float abm = 0.25f * (ab[0] + ab[1] + ab[2] + ab[3]);
    const int c4 = lane * 4;
    const float4 g4 = *(const float4*)(eng + c4);
    const float4 b4 = *(const float4*)(enb + c4);
    float4 t0 = *(const float4*)(aw + (256 + c4) * 4);
    float4 t1 = *(const float4*)(aw + (256 + c4 + 1) * 4);
    float4 t2 = *(const float4*)(aw + (256 + c4 + 2) * 4);
    float4 t3 = *(const float4*)(aw + (256 + c4 + 3) * 4);
    const float wa0 = t0.x + t0.y + t0.z + t0.w;
    const float wa1 = t1.x + t1.y + t1.z + t1.w;
    const float wa2 = t2.x + t2.y + t2.z + t2.w;
    const float wa3 = t3.x + t3.y + t3.z + t3.w;
#pragma unroll 1
    for (int rr = 0; rr < 16; rr++) {
        const int row = wid * 16 + rr;
        float4 v = *(const float4*)(X + row * 132 + c4);
        float mean = wred(v.x + v.y + v.z + v.w) * (1.f / 128.f);
        float dx = v.x - mean, dy = v.y - mean, dz = v.z - mean, dw = v.w - mean;
        float var = wred(dx * dx + dy * dy + dz * dz + dw * dw) * (1.f / 128.f);
        float rstd = rsqrtf(var + 1e-5f);
        float4 y;
        y.x = dx * rstd * g4.x + b4.x;
        y.y = dy * rstd * g4.y + b4.y;
        y.z = dz * rstd * g4.z + b4.z;
        y.w = dw * rstd * g4.w + b4.w;
        *(float4*)(e_out + (size_t)(e0 + row) * 128 + c4) = y;
        float sp = wred(y.x * wa0 + y.y * wa1 + y.z * wa2 + y.w * wa3);
        if (lane == 0) {
            int dd = didx[row];
            float sc = sp * 0.25f + g_node_score[dd] + abm;
            g_scores[e0 + row] = sc;
            atomicMax(&g_segmax[dd], f2o(sc));
        }
    }
}

// ---------------- K2: ex = exp(score - segmax[dst]); se[dst] += ex ----------------
__global__ void k2_exp(const int* __restrict__ ei) {
    int e = blockIdx.x * 256 + threadIdx.x;
    if (e >= EE) return;
    int d = ei[EE + e];
    float ex = expf(g_scores[e] - o2f(g_segmax[d]));
    g_ex[e] = ex;
    atomicAdd(&g_se[d], ex);
}

// ---------------- K3: agg[dst] += w_e * e_e ----------------
__global__ void k3_scatter(const int* __restrict__ ei, const float* __restrict__ e_feat) {
    int e = blockIdx.x * 2 + (threadIdx.x >> 7);
    int c = threadIdx.x & 127;
    int d = ei[EE + e];
    float w = g_ex[e] / (g_se[d] + 1e-6f);
    atomicAdd(&g_agg[(size_t)d * 128 + c], w * e_feat[(size_t)e * 128 + c]);
}

// ---------------- K4: node update (3 fused GEMMs + residual + LN), f32x2 ----------------
template <int KDIM, int NCOLS>
__device__ __forceinline__ void gemm_smem(const float* Xs, int ldx,
                                          const float* __restrict__ Bg,
                                          float* Bs, ull* acc, int tid) {
    constexpr int NP = NCOLS / 32;
    const int tx = tid & 15, ty = tid >> 4;
#pragma unroll 1
    for (int k0 = 0; k0 < KDIM; k0 += 16) {
        __syncthreads();
        constexpr int NF4 = 16 * NCOLS / 4;
#pragma unroll
        for (int j = 0; j < NF4 / 256; j++) {
            int f = tid + j * 256;
            int rr = f / (NCOLS / 4);
            int cc = (f - rr * (NCOLS / 4)) * 4;
            *(float4*)(Bs + rr * NCOLS + cc) = *(const float4*)(Bg + (size_t)(k0 + rr) * NCOLS + cc);
        }
        __syncthreads();
#pragma unroll
        for (int kk = 0; kk < 16; kk++) {
            ull aa[4];
#pragma unroll
            for (int i = 0; i < 4; i++) { float a = Xs[(ty * 4 + i) * ldx + k0 + kk]; aa[i] = pk(a, a); }
#pragma unroll
            for (int p = 0; p < NP; p++) {
                ull bb = *(const ull*)(Bs + kk * NCOLS + (tx + 16 * p) * 2);
#pragma unroll
                for (int i = 0; i < 4; i++) fma2(acc[i * NP + p], aa[i], bb);
            }
        }
    }
    __syncthreads();
}

__global__ __launch_bounds__(256, 2) void k4_node(
    const float* __restrict__ nf,
    const float* __restrict__ evw, const float* __restrict__ evb,
    const float* __restrict__ ow1, const float* __restrict__ ob1,
    const float* __restrict__ ow2, const float* __restrict__ ob2,
    const float* __restrict__ nng, const float* __restrict__ nnb,
    float* __restrict__ n_out) {
    extern __shared__ float sm[];
    float* X  = sm;              // 64*256
    float* Bs = X + 64 * 256;    // 16*256
    float* sw = Bs + 16 * 256;   // 64
    const int tid = threadIdx.x;
    const int tx = tid & 15, ty = tid >> 4;
    const int n0 = blockIdx.x * 64;
#pragma unroll
    for (int j = 0; j < 8; j++) {
        int f = tid + j * 256;
        int rr = f >> 5; int cc = (f & 31) * 4;
        float4 v = make_float4(0.f, 0.f, 0.f, 0.f);
        if (n0 + rr < NN) v = *(const float4*)(g_agg + (size_t)(n0 + rr) * 128 + cc);
        *(float4*)(X + rr * 128 + cc) = v;
    }
    if (tid < 64) {
        int nn2 = n0 + tid;
        float se = (nn2 < NN) ? g_se[nn2] : 0.f;
        sw[tid] = se / (se + 1e-6f);
    }
    ull acc[32];
#pragma unroll
    for (int i = 0; i < 32; i++) acc[i] = 0ull;
    gemm_smem<128, 256>(X, 128, evw, Bs, acc, tid);
#pragma unroll
    for (int i = 0; i < 4; i++) {
        int rr = ty * 4 + i;
        float s = sw[rr];
#pragma unroll
        for (int p = 0; p < 8; p++) {
            int c0 = (tx + 16 * p) * 2;
            float2 v = upk(acc[i * 8 + p]);
            v.x += s * evb[c0];
            v.y += s * evb[c0 + 1];
            *(float2*)(X + rr * 256 + c0) = v;
        }
    }
#pragma unroll
    for (int i = 0; i < 32; i++) acc[i] = 0ull;
    gemm_smem<256, 256>(X, 256, ow1, Bs, acc, tid);
#pragma unroll
    for (int i = 0; i < 4; i++) {
        int rr = ty * 4 + i;
#pragma unroll
        for (int p = 0; p < 8; p++) {
            int c0 = (tx + 16 * p) * 2;
            float2 v = upk(acc[i * 8 + p]);
            v.x = fmaxf(v.x + ob1[c0], 0.f);
            v.y = fmaxf(v.y + ob1[c0 + 1], 0.f);
            *(float2*)(X + rr * 256 + c0) = v;
        }
    }
#pragma unroll
    for (int i = 0; i < 32; i++) acc[i] = 0ull;
    gemm_smem<256, 256>(X, 256, ow2, Bs, acc, tid);
#pragma unroll
    for (int i = 0; i < 4; i++) {
        int rr = ty * 4 + i;
        int row = n0 + rr;
#pragma unroll
        for (int p = 0; p < 8; p++) {
            int c0 = (tx + 16 * p) * 2;
            float2 v = upk(acc[i * 8 + p]);
            v.x += ob2[c0];
            v.y += ob2[c0 + 1];
            if (row < NN) {
                v.x += nf[(size_t)row * 256 + c0];
                v.y += nf[(size_t)row * 256 + c0 + 1];
            }
            *(float2*)(X + rr * 256 + c0) = v;
        }
    }
    __syncthreads();
    const int wp = tid >> 5, lane = tid & 31;
    const int cb = lane * 8;
    float4 g0 = *(const float4*)(nng + cb), g1 = *(const float4*)(nng + cb + 4);
    float4 h0 = *(const float4*)(nnb + cb), h1 = *(const float4*)(nnb + cb + 4);
#pragma unroll 1
    for (int rr = 0; rr < 8; rr++) {
        int rrow = wp * 8 + rr;
        int row = n0 + rrow;
        float4 v0 = *(const float4*)(X + rrow * 256 + cb);
        float4 v1 = *(const float4*)(X + rrow * 256 + cb + 4);
        float mean = wred(v0.x + v0.y + v0.z + v0.w + v1.x + v1.y + v1.z + v1.w) * (1.f / 256.f);
        float d0x = v0.x - mean, d0y = v0.y - mean, d0z = v0.z - mean, d0w = v0.w - mean;
        float d1x = v1.x - mean, d1y = v1.y - mean, d1z = v1.z - mean, d1w = v1.w - mean;
        float var = wred(d0x * d0x + d0y * d0y + d0z * d0z + d0w * d0w +
                         d1x * d1x + d1y * d1y + d1z * d1z + d1w * d1w) * (1.f / 256.f);
        float rstd = rsqrtf(var + 1e-5f);
        if (row < NN) {
            float4 y0, y1;
            y0.x = d0x * rstd * g0.x + h0.x; y0.y = d0y * rstd * g0.y + h0.y;
            y0.z = d0z * rstd * g0.z + h0.z; y0.w = d0w * rstd * g0.w + h0.w;
            y1.x = d1x * rstd * g1.x + h1.x; y1.y = d1y * rstd * g1.y + h1.y;
            y1.z = d1z * rstd * g1.z + h1.z; y1.w = d1w * rstd * g1.w + h1.w;
            *(float4*)(n_out + (size_t)row * 256 + cb) = y0;
            *(float4*)(n_out + (size_t)row * 256 + cb + 4) = y1;
        }
    }
}

// ---------------- launch ----------------
extern "C" void kernel_launch(void* const* d_in, const int* in_sizes, int n_in,
                              void* d_out, int out_size) {
    const float* nf  = (const float*)d_in[0];
    const float* ef  = (const float*)d_in[1];
    const int*   ei  = (const int*)d_in[2];
    const float* ew1 = (const float*)d_in[3];
    const float* eb1 = (const float*)d_in[4];
    const float* ew2 = (const float*)d_in[5];
    const float* eb2 = (const float*)d_in[6];
    const float* eng = (const float*)d_in[7];
    const float* enb = (const float*)d_in[8];
    const float* aw  = (const float*)d_in[9];
    const float* ab  = (const float*)d_in[10];
    const float* evw = (const float*)d_in[11];
    const float* evb = (const float*)d_in[12];
    const float* ow1 = (const float*)d_in[13];
    const float* ob1 = (const float*)d_in[14];
    const float* ow2 = (const float*)d_in[15];
    const float* ob2 = (const float*)d_in[16];
    const float* nng = (const float*)d_in[17];
    const float* nnb = (const float*)d_in[18];

    float* out = (float*)d_out;
    float* n_out = out;                        // (N, 256)
    float* e_out = out + (size_t)NN * 256;     // (E, 128)

    const int SMEM4 = (64 * 256 + 16 * 256 + 64) * 4;
    cudaFuncSetAttribute(k1_edge_mma, cudaFuncAttributeMaxDynamicSharedMemorySize, SMEM_K1);
    cudaFuncSetAttribute(k4_node, cudaFuncAttributeMaxDynamicSharedMemorySize, SMEM4);

    k_prep<<<768, 256>>>(ew1, ew2);
    k0_node_prep<<<(NN + 7) / 8, 256>>>(nf, aw);
    k1_edge_mma<<<TILES, 256, SMEM_K1>>>(nf, ef, ei, eb1, eb2, eng, enb, aw, ab, e_out);
    k2_exp<<<(EE + 255) / 256, 256>>>(ei);
    k3_scatter<<<EE / 2, 256>>>(ei, e_out);
    k4_node<<<(NN + 63) / 64, 256, SMEM4>>>(nf, evw, evb, ow1, ob1, ow2, ob2, nng, nnb, n_out);
}

// round 10
// speedup vs baseline: 1.1496x; 1.0600x over previous
#include <cuda_runtime.h>
#include <cuda_bf16.h>
#include <cstdint>

#define NN 25000
#define EE 400000
#define TILES (EE / 128)   // 3125

typedef unsigned long long ull;

// ---- scratch (static device globals; no allocation) ----
__device__ float g_node_score[NN];
__device__ int   g_segmax[NN];
__device__ float g_se[NN];
__device__ float g_agg[(size_t)NN * 128];
__device__ float g_scores[EE];
__device__ float g_ex[EE];
// pre-split / transposed weights (bf16 hi/lo), K-major [N][K]
__device__ __nv_bfloat16 g_w1t_hi[256 * 640];
__device__ __nv_bfloat16 g_w1t_lo[256 * 640];
__device__ __nv_bfloat16 g_w2t_hi[128 * 256];
__device__ __nv_bfloat16 g_w2t_lo[128 * 256];

// ---- generic helpers ----
__device__ __forceinline__ ull pk(float lo, float hi) {
    ull r; asm("mov.b64 %0, {%1,%2};" : "=l"(r) : "f"(lo), "f"(hi)); return r;
}
__device__ __forceinline__ float2 upk(ull v) {
    float2 r; asm("mov.b64 {%0,%1}, %2;" : "=f"(r.x), "=f"(r.y) : "l"(v)); return r;
}
__device__ __forceinline__ void fma2(ull& d, ull a, ull b) {
    asm("fma.rn.f32x2 %0, %1, %2, %0;" : "+l"(d) : "l"(a), "l"(b));
}
__device__ __forceinline__ float wred(float v) {
#pragma unroll
    for (int o = 16; o; o >>= 1) v += __shfl_xor_sync(0xffffffffu, v, o);
    return v;
}
__device__ __forceinline__ int f2o(float f) { int i = __float_as_int(f); return i >= 0 ? i : i ^ 0x7fffffff; }
__device__ __forceinline__ float o2f(int i) { return __int_as_float(i >= 0 ? i : i ^ 0x7fffffff); }
__device__ __forceinline__ uint32_t smem_u32(const void* p) {
    uint32_t a; asm("{ .reg .u64 t; cvta.to.shared.u64 t, %1; cvt.u32.u64 %0, t; }" : "=r"(a) : "l"(p));
    return a;
}

// pack (lo -> lower 16, hi -> upper 16) as bf16x2
__device__ __forceinline__ uint32_t bfpair(float lo, float hi) {
    uint32_t u; asm("cvt.rn.bf16x2.f32 %0, %1, %2;" : "=r"(u) : "f"(hi), "f"(lo)); return u;
}
__device__ __forceinline__ float bflo(uint32_t u) { return __uint_as_float(u << 16); }
__device__ __forceinline__ float bfhi(uint32_t u) { return __uint_as_float(u & 0xffff0000u); }

__device__ __forceinline__ void split8(float4 a, float4 b, uint4& hv, uint4& lv) {
    uint32_t u0 = bfpair(a.x, a.y);
    uint32_t u1 = bfpair(a.z, a.w);
    uint32_t u2 = bfpair(b.x, b.y);
    uint32_t u3 = bfpair(b.z, b.w);
    uint32_t l0 = bfpair(a.x - bflo(u0), a.y - bfhi(u0));
    uint32_t l1 = bfpair(a.z - bflo(u1), a.w - bfhi(u1));
    uint32_t l2 = bfpair(b.x - bflo(u2), b.y - bfhi(u2));
    uint32_t l3 = bfpair(b.z - bflo(u3), b.w - bfhi(u3));
    hv = make_uint4(u0, u1, u2, u3);
    lv = make_uint4(l0, l1, l2, l3);
}

// warp-level bf16 MMA (sm_80+ baseline PTX; valid on plain sm_100 target)
__device__ __forceinline__ void mma16816(float* d, const uint32_t* a, uint32_t b0, uint32_t b1) {
    asm volatile(
        "mma.sync.aligned.m16n8k16.row.col.f32.bf16.bf16.f32 "
        "{%0,%1,%2,%3}, {%4,%5,%6,%7}, {%8,%9}, {%0,%1,%2,%3};"
        : "+f"(d[0]), "+f"(d[1]), "+f"(d[2]), "+f"(d[3])
        : "r"(a[0]), "r"(a[1]), "r"(a[2]), "r"(a[3]), "r"(b0), "r"(b1));
}

// ldmatrix x4 (sm_75+ baseline)
__device__ __forceinline__ void ldmx4(uint32_t* r, uint32_t addr) {
    asm volatile("ldmatrix.sync.aligned.m8n8.x4.shared.b16 {%0,%1,%2,%3}, [%4];"
                 : "=r"(r[0]), "=r"(r[1]), "=r"(r[2]), "=r"(r[3]) : "r"(addr));
}

// ---------------- prep: transpose + bf16-split weights ----------------
__global__ void k_prep(const float* __restrict__ ew1, const float* __restrict__ ew2) {
    int i = blockIdx.x * 256 + threadIdx.x;
    if (i < 256 * 640) {
        int n = i / 640, k = i - n * 640;
        float x = ew1[(size_t)k * 256 + n];
        __nv_bfloat16 h = __float2bfloat16(x);
        g_w1t_hi[i] = h;
        g_w1t_lo[i] = __float2bfloat16(x - __bfloat162float(h));
    } else {
        int j = i - 256 * 640;
        if (j < 128 * 256) {
            int n = j / 256, k = j - n * 256;
            float x = ew2[(size_t)k * 128 + n];
            __nv_bfloat16 h = __float2bfloat16(x);
            g_w2t_hi[j] = h;
            g_w2t_lo[j] = __float2bfloat16(x - __bfloat162float(h));
        }
    }
}

// ---------------- K0: per-node attention-score part + scratch init ----------------
__global__ void k0_node_prep(const float* __restrict__ nf, const float* __restrict__ aw) {
    int node = blockIdx.x * 8 + (threadIdx.x >> 5);
    int lane = threadIdx.x & 31;
    if (node >= NN) return;
    const float* row = nf + (size_t)node * 256;
    float s = 0.f;
#pragma unroll
    for (int c = lane; c < 256; c += 32) {
        const float4 a = *(const float4*)(aw + c * 4);
        s += row[c] * (a.x + a.y + a.z + a.w);
    }
    s = wred(s);
    if (lane == 0) {
        g_node_score[node] = s * 0.25f;
        g_segmax[node] = (int)0x80000000;
        g_se[node] = 0.f;
    }
    float* ag = g_agg + (size_t)node * 128;
    for (int c = lane; c < 128; c += 32) ag[c] = 0.f;
}

// ---------------- K1: warp-MMA bf16-split fused edge MLP (ldmatrix + reg pipelining) ----------------
// SMEM layout (bytes), rows padded to 72 bf16 (144B = 9 x 16B granules, conflict-free):
//  0:     sidx[128] | 512: didx[128]
//  1024:  A chunk hi [128][72]  (18432)     (also X fp32 [128][132] = 67584 in epilogue2)
//  19456: A chunk lo            (18432)
//  37888: B chunk hi            (18432)
//  56320: B chunk lo            (18432)
//  74752: H chunks: 4 x (hi 18432 + lo 18432) = 147456  -> total 222208
#define OFF_AH 1024
#define OFF_AL 19456
#define OFF_BH 37888
#define OFF_BL 56320
#define OFF_H  74752
#define OFF_X  1024
#define SMEM_K1 222208

// 3-pass split MMA over one 64-K chunk: acc += Ah*Bh + Ah*Bl + Al*Bh
__device__ __forceinline__ void mma_chunk(float acc[2][8][4],
                                          uint32_t shAH, uint32_t shAL,
                                          uint32_t shBH, uint32_t shBL) {
#pragma unroll
    for (int ks = 0; ks < 4; ks++) {
        const uint32_t kb2 = ks * 32;  // k-bytes
        uint32_t Ah[2][4], Al[2][4];
#pragma unroll
        for (int mt = 0; mt < 2; mt++) {
            ldmx4(Ah[mt], shAH + mt * 2304 + kb2);
            ldmx4(Al[mt], shAL + mt * 2304 + kb2);
        }
#pragma unroll
        for (int ntp = 0; ntp < 4; ntp++) {
            uint32_t bh[4], bl[4];
            ldmx4(bh, shBH + ntp * 2304 + kb2);
            ldmx4(bl, shBL + ntp * 2304 + kb2);
#pragma unroll
            for (int hf = 0; hf < 2; hf++) {
                const int nt = ntp * 2 + hf;
                uint32_t b0h = bh[hf * 2], b1h = bh[hf * 2 + 1];
                uint32_t b0l = bl[hf * 2], b1l = bl[hf * 2 + 1];
                mma16816(acc[0][nt], Ah[0], b0h, b1h);
                mma16816(acc[1][nt], Ah[1], b0h, b1h);
                mma16816(acc[0][nt], Ah[0], b0l, b1l);
                mma16816(acc[1][nt], Ah[1], b0l, b1l);
                mma16816(acc[0][nt], Al[0], b0h, b1h);
                mma16816(acc[1][nt], Al[1], b0h, b1h);
            }
        }
    }
}

__global__ __launch_bounds__(256, 1) void k1_edge_mma(
    const float* __restrict__ nf, const float* __restrict__ ef, const int* __restrict__ ei,
    const float* __restrict__ eb1, const float* __restrict__ eb2,
    const float* __restrict__ eng, const float* __restrict__ enb,
    const float* __restrict__ aw, const float* __restrict__ ab,
    float* __restrict__ e_out) {
    extern __shared__ char smb[];
    int* sidx = (int*)smb;
    int* didx = (int*)(smb + 512);
    const int tid = threadIdx.x;
    const int wid = tid >> 5, lane = tid & 31;
    const int wm = wid >> 1, wn = wid & 1;
    const int m0 = wm * 32;
    const int qr = lane >> 2;         // 0..7
    const int qc = (lane & 3) * 2;    // 0,2,4,6
    const int e0 = blockIdx.x * 128;

    if (tid < 128) sidx[tid] = ei[e0 + tid];
    else didx[tid - 128] = ei[EE + e0 + tid - 128];
    __syncthreads();

    // per-lane ldmatrix base addresses
    const uint32_t sbase = smem_u32(smb);
    const int mrow = (lane & 7) + (((lane >> 3) & 1) << 3);   // row within 16 (A)
    const uint32_t aOff = (uint32_t)((m0 + mrow) * 144 + ((lane >> 4) << 4));
    const int brow = (lane & 7) + ((lane >> 4) << 3);          // row within 16 (B)
    const uint32_t bOff = (uint32_t)((wn * 64 + brow) * 144 + (((lane >> 3) & 1) << 4));
    const uint32_t shAH = sbase + OFF_AH + aOff;
    const uint32_t shAL = sbase + OFF_AL + aOff;
    const uint32_t shBH = sbase + OFF_BH + bOff;
    const uint32_t shBL = sbase + OFF_BL + bOff;

    // producer prefetch registers
    float4 pfA[8];
    uint4  pfW[8];
    const int arow = tid >> 1, ach = (tid & 1) * 32;
    const int wrow = tid & 127;

    auto ldA = [&](int c) {
        const int kg = c * 64;
        const float* base;
        if (kg < 256)      base = nf + (size_t)sidx[arow] * 256 + kg;
        else if (kg < 512) base = nf + (size_t)didx[arow] * 256 + (kg - 256);
        else               base = ef + (size_t)(e0 + arow) * 128 + (kg - 512);
#pragma unroll
        for (int g = 0; g < 4; g++) {
            pfA[2 * g]     = *(const float4*)(base + ach + g * 8);
            pfA[2 * g + 1] = *(const float4*)(base + ach + g * 8 + 4);
        }
    };
    auto ldW1 = [&](int h, int c) {
        const __nv_bfloat16* src =
            (tid < 128 ? g_w1t_hi : g_w1t_lo) + (size_t)(h * 128 + wrow) * 640 + c * 64;
#pragma unroll
        for (int g = 0; g < 8; g++) pfW[g] = *(const uint4*)(src + g * 8);
    };
    auto ldW2 = [&](int c) {
        const __nv_bfloat16* src =
            (tid < 128 ? g_w2t_hi : g_w2t_lo) + (size_t)wrow * 256 + c * 64;
#pragma unroll
        for (int g = 0; g < 8; g++) pfW[g] = *(const uint4*)(src + g * 8);
    };
    auto stA = [&]() {
        char* ah = smb + OFF_AH;
        char* al = smb + OFF_AL;
#pragma unroll
        for (int g = 0; g < 4; g++) {
            uint4 hv, lv; split8(pfA[2 * g], pfA[2 * g + 1], hv, lv);
            const uint32_t off = (uint32_t)(arow * 144 + (ach + g * 8) * 2);
            *(uint4*)(ah + off) = hv;
            *(uint4*)(al + off) = lv;
        }
    };
    auto stW = [&]() {
        char* dst = smb + (tid < 128 ? OFF_BH : OFF_BL) + wrow * 144;
#pragma unroll
        for (int g = 0; g < 8; g++) *(uint4*)(dst + g * 16) = pfW[g];
    };

    float acc[2][8][4];
#pragma unroll
    for (int mt = 0; mt < 2; mt++)
#pragma unroll
        for (int nt = 0; nt < 8; nt++)
#pragma unroll
            for (int q = 0; q < 4; q++) acc[mt][nt][q] = 0.f;

    // ================= phase 1: 20 pipelined chunks (2 N-halves x 10 K-chunks) =================
    ldA(0); ldW1(0, 0);
#pragma unroll 1
    for (int st = 0; st < 20; st++) {
        const int h = st / 10, c = st % 10;
        __syncthreads();          // consumers done with buffers
        stA(); stW();
        __syncthreads();          // buffers ready
        if (st < 19) { ldA((st + 1) % 10); ldW1((st + 1) / 10, (st + 1) % 10); }
        else ldW2(0);
        mma_chunk(acc, shAH, shAL, shBH, shBL);
        if (c == 9) {
            // epilogue 1: bias + relu + bf16-split -> H chunk (h*2 + wn)
            char* Hh = smb + OFF_H + (h * 2 + wn) * 36864;
            char* Hl = Hh + 18432;
#pragma unroll
            for (int mt = 0; mt < 2; mt++)
#pragma unroll
                for (int nt = 0; nt < 8; nt++) {
                    const int gcol = h * 128 + wn * 64 + nt * 8 + qc;
                    const float b0v = eb1[gcol], b1v = eb1[gcol + 1];
                    const int row = m0 + mt * 16 + qr;
                    const int colc = nt * 8 + qc;
                    float f0 = fmaxf(acc[mt][nt][0] + b0v, 0.f);
                    float f1 = fmaxf(acc[mt][nt][1] + b1v, 0.f);
                    uint32_t uh = bfpair(f0, f1);
                    *(uint32_t*)(Hh + row * 144 + colc * 2) = uh;
                    *(uint32_t*)(Hl + row * 144 + colc * 2) = bfpair(f0 - bflo(uh), f1 - bfhi(uh));
                    float f2 = fmaxf(acc[mt][nt][2] + b0v, 0.f);
                    float f3 = fmaxf(acc[mt][nt][3] + b1v, 0.f);
                    uint32_t uh2 = bfpair(f2, f3);
                    *(uint32_t*)(Hh + (row + 8) * 144 + colc * 2) = uh2;
                    *(uint32_t*)(Hl + (row + 8) * 144 + colc * 2) = bfpair(f2 - bflo(uh2), f3 - bfhi(uh2));
                }
#pragma unroll
            for (int mt = 0; mt < 2; mt++)
#pragma unroll
                for (int nt = 0; nt < 8; nt++)
#pragma unroll
                    for (int q = 0; q < 4; q++) acc[mt][nt][q] = 0.f;
        }
    }

    // ================= phase 2: H(128x256) @ W2(256x128), 4 pipelined chunks =================
#pragma unroll 1
    for (int c2 = 0; c2 < 4; c2++) {
        __syncthreads();
        stW();
        __syncthreads();
        if (c2 < 3) ldW2(c2 + 1);
        const uint32_t shH = sbase + OFF_H + c2 * 36864 + aOff;
        mma_chunk(acc, shH, shH + 18432, shBH, shBL);
    }

    // ================= epilogue 2: bias + residual -> X, LN, score =================
    __syncthreads();
    float* X = (float*)(smb + OFF_X);
#pragma unroll
    for (int mt = 0; mt < 2; mt++)
#pragma unroll
        for (int nt = 0; nt < 8; nt++) {
            const int col = wn * 64 + nt * 8 + qc;
            const float b0v = eb2[col], b1v = eb2[col + 1];
            const int row = m0 + mt * 16 + qr;
            float2 v0, v1;
            v0.x = acc[mt][nt][0] + b0v + ef[(size_t)(e0 + row) * 128 + col];
            v0.y = acc[mt][nt][1] + b1v + ef[(size_t)(e0 + row) * 128 + col + 1];
            v1.x = acc[mt][nt][2] + b0v + ef[(size_t)(e0 + row + 8) * 128 + col];
            v1.y = acc[mt][nt][3] + b1v + ef[(size_t)(e0 + row + 8) * 128 + col + 1];
            *(float2*)(X + row * 132 + col) = v0;
            *(float2*)(X + (row + 8) * 132 + col) = v1;
        }
    __syncthreads();

    const float abm = 0.25f * (ab[0] + ab[1] + ab[2] + ab[3]);
    const int c4 = lane * 4;
    const float4 g4 = *(const float4*)(eng + c4);
    const float4 b4 = *(const float4*)(enb + c4);
    float4 t0 = *(const float4*)(aw + (256 + c4) * 4);
    float4 t1 = *(const float4*)(aw + (256 + c4 + 1) * 4);
    float4 t2 = *(const float4*)(aw + (256 + c4 + 2) * 4);
    float4 t3 = *(const float4*)(aw + (256 + c4 + 3) * 4);
    const float wa0 = t0.x + t0.y + t0.z + t0.w;
    const float wa1 = t1.x + t1.y + t1.z + t1.w;
    const float wa2 = t2.x + t2.y + t2.z + t2.w;
    const float wa3 = t3.x + t3.y + t3.z + t3.w;
#pragma unroll 1
    for (int rr = 0; rr < 16; rr++) {
        const int row = wid * 16 + rr;
        float4 v = *(const float4*)(X + row * 132 + c4);
        float mean = wred(v.x + v.y + v.z + v.w) * (1.f / 128.f);
        float dx = v.x - mean, dy = v.y - mean, dz = v.z - mean, dw = v.w - mean;
        float var = wred(dx * dx + dy * dy + dz * dz + dw * dw) * (1.f / 128.f);
        float rstd = rsqrtf(var + 1e-5f);
        float4 y;
        y.x = dx * rstd * g4.x + b4.x;
        y.y = dy * rstd * g4.y + b4.y;
        y.z = dz * rstd * g4.z + b4.z;
        y.w = dw * rstd * g4.w + b4.w;
        *(float4*)(e_out + (size_t)(e0 + row) * 128 + c4) = y;
        float sp = wred(y.x * wa0 + y.y * wa1 + y.z * wa2 + y.w * wa3);
        if (lane == 0) {
            int dd = didx[row];
            float sc = sp * 0.25f + g_node_score[dd] + abm;
            g_scores[e0 + row] = sc;
            atomicMax(&g_segmax[dd], f2o(sc));
        }
    }
}

// ---------------- K2: ex = exp(score - segmax[dst]); se[dst] += ex ----------------
__global__ void k2_exp(const int* __restrict__ ei) {
    int e = blockIdx.x * 256 + threadIdx.x;
    if (e >= EE) return;
    int d = ei[EE + e];
    float ex = expf(g_scores[e] - o2f(g_segmax[d]));
    g_ex[e] = ex;
    atomicAdd(&g_se[d], ex);
}

// ---------------- K3: agg[dst] += w_e * e_e ----------------
__global__ void k3_scatter(const int* __restrict__ ei, const float* __restrict__ e_feat) {
    int e = blockIdx.x * 2 + (threadIdx.x >> 7);
    int c = threadIdx.x & 127;
    int d = ei[EE + e];
    float w = g_ex[e] / (g_se[d] + 1e-6f);
    atomicAdd(&g_agg[(size_t)d * 128 + c], w * e_feat[(size_t)e * 128 + c]);
}

// ---------------- K4: node update (3 fused GEMMs + residual + LN), f32x2 ----------------
template <int KDIM, int NCOLS>
__device__ __forceinline__ void gemm_smem(const float* Xs, int ldx,
                                          const float* __restrict__ Bg,
                                          float* Bs, ull* acc, int tid) {
    constexpr int NP = NCOLS / 32;
    const int tx = tid & 15, ty = tid >> 4;
#pragma unroll 1
    for (int k0 = 0; k0 < KDIM; k0 += 16) {
        __syncthreads();
        constexpr int NF4 = 16 * NCOLS / 4;
#pragma unroll
        for (int j = 0; j < NF4 / 256; j++) {
            int f = tid + j * 256;
            int rr = f / (NCOLS / 4);
            int cc = (f - rr * (NCOLS / 4)) * 4;
            *(float4*)(Bs + rr * NCOLS + cc) = *(const float4*)(Bg + (size_t)(k0 + rr) * NCOLS + cc);
        }
        __syncthreads();
#pragma unroll
        for (int kk = 0; kk < 16; kk++) {
            ull aa[4];
#pragma unroll
            for (int i = 0; i < 4; i++) { float a = Xs[(ty * 4 + i) * ldx + k0 + kk]; aa[i] = pk(a, a); }
#pragma unroll
            for (int p = 0; p < NP; p++) {
                ull bb = *(const ull*)(Bs + kk * NCOLS + (tx + 16 * p) * 2);
#pragma unroll
                for (int i = 0; i < 4; i++) fma2(acc[i * NP + p], aa[i], bb);
            }
        }
    }
    __syncthreads();
}

__global__ __launch_bounds__(256, 2) void k4_node(
    const float* __restrict__ nf,
    const float* __restrict__ evw, const float* __restrict__ evb,
    const float* __restrict__ ow1, const float* __restrict__ ob1,
    const float* __restrict__ ow2, const float* __restrict__ ob2,
    const float* __restrict__ nng, const float* __restrict__ nnb,
    float* __restrict__ n_out) {
    extern __shared__ float sm[];
    float* X  = sm;              // 64*256
    float* Bs = X + 64 * 256;    // 16*256
    float* sw = Bs + 16 * 256;   // 64
    const int tid = threadIdx.x;
    const int tx = tid & 15, ty = tid >> 4;
    const int n0 = blockIdx.x * 64;
#pragma unroll
    for (int j = 0; j < 8; j++) {
        int f = tid + j * 256;
        int rr = f >> 5; int cc = (f & 31) * 4;
        float4 v = make_float4(0.f, 0.f, 0.f, 0.f);
        if (n0 + rr < NN) v = *(const float4*)(g_agg + (size_t)(n0 + rr) * 128 + cc);
        *(float4*)(X + rr * 128 + cc) = v;
    }
    if (tid < 64) {
        int nn2 = n0 + tid;
        float se = (nn2 < NN) ? g_se[nn2] : 0.f;
        sw[tid] = se / (se + 1e-6f);
    }
    ull acc[32];
#pragma unroll
    for (int i = 0; i < 32; i++) acc[i] = 0ull;
    gemm_smem<128, 256>(X, 128, evw, Bs, acc, tid);
#pragma unroll
    for (int i = 0; i < 4; i++) {
        int rr = ty * 4 + i;
        float s = sw[rr];
#pragma unroll
        for (int p = 0; p < 8; p++) {
            int c0 = (tx + 16 * p) * 2;
            float2 v = upk(acc[i * 8 + p]);
            v.x += s * evb[c0];
            v.y += s * evb[c0 + 1];
            *(float2*)(X + rr * 256 + c0) = v;
        }
    }
#pragma unroll
    for (int i = 0; i < 32; i++) acc[i] = 0ull;
    gemm_smem<256, 256>(X, 256, ow1, Bs, acc, tid);
#pragma unroll
    for (int i = 0; i < 4; i++) {
        int rr = ty * 4 + i;
#pragma unroll
        for (int p = 0; p < 8; p++) {
            int c0 = (tx + 16 * p) * 2;
            float2 v = upk(acc[i * 8 + p]);
            v.x = fmaxf(v.x + ob1[c0], 0.f);
            v.y = fmaxf(v.y + ob1[c0 + 1], 0.f);
            *(float2*)(X + rr * 256 + c0) = v;
        }
    }
#pragma unroll
    for (int i = 0; i < 32; i++) acc[i] = 0ull;
    gemm_smem<256, 256>(X, 256, ow2, Bs, acc, tid);
#pragma unroll
    for (int i = 0; i < 4; i++) {
        int rr = ty * 4 + i;
        int row = n0 + rr;
#pragma unroll
        for (int p = 0; p < 8; p++) {
            int c0 = (tx + 16 * p) * 2;
            float2 v = upk(acc[i * 8 + p]);
            v.x += ob2[c0];
            v.y += ob2[c0 + 1];
            if (row < NN) {
                v.x += nf[(size_t)row * 256 + c0];
                v.y += nf[(size_t)row * 256 + c0 + 1];
            }
            *(float2*)(X + rr * 256 + c0) = v;
        }
    }
    __syncthreads();
    const int wp = tid >> 5, lane = tid & 31;
    const int cb = lane * 8;
    float4 g0 = *(const float4*)(nng + cb), g1 = *(const float4*)(nng + cb + 4);
    float4 h0 = *(const float4*)(nnb + cb), h1 = *(const float4*)(nnb + cb + 4);
#pragma unroll 1
    for (int rr = 0; rr < 8; rr++) {
        int rrow = wp * 8 + rr;
        int row = n0 + rrow;
        float4 v0 = *(const float4*)(X + rrow * 256 + cb);
        float4 v1 = *(const float4*)(X + rrow * 256 + cb + 4);
        float mean = wred(v0.x + v0.y + v0.z + v0.w + v1.x + v1.y + v1.z + v1.w) * (1.f / 256.f);
        float d0x = v0.x - mean, d0y = v0.y - mean, d0z = v0.z - mean, d0w = v0.w - mean;
        float d1x = v1.x - mean, d1y = v1.y - mean, d1z = v1.z - mean, d1w = v1.w - mean;
        float var = wred(d0x * d0x + d0y * d0y + d0z * d0z + d0w * d0w +
                         d1x * d1x + d1y * d1y + d1z * d1z + d1w * d1w) * (1.f / 256.f);
        float rstd = rsqrtf(var + 1e-5f);
        if (row < NN) {
            float4 y0, y1;
            y0.x = d0x * rstd * g0.x + h0.x; y0.y = d0y * rstd * g0.y + h0.y;
            y0.z = d0z * rstd * g0.z + h0.z; y0.w = d0w * rstd * g0.w + h0.w;
            y1.x = d1x * rstd * g1.x + h1.x; y1.y = d1y * rstd * g1.y + h1.y;
            y1.z = d1z * rstd * g1.z + h1.z; y1.w = d1w * rstd * g1.w + h1.w;
            *(float4*)(n_out + (size_t)row * 256 + cb) = y0;
            *(float4*)(n_out + (size_t)row * 256 + cb + 4) = y1;
        }
    }
}

// ---------------- launch ----------------
extern "C" void kernel_launch(void* const* d_in, const int* in_sizes, int n_in,
                              void* d_out, int out_size) {
    const float* nf  = (const float*)d_in[0];
    const float* ef  = (const float*)d_in[1];
    const int*   ei  = (const int*)d_in[2];
    const float* ew1 = (const float*)d_in[3];
    const float* eb1 = (const float*)d_in[4];
    const float* ew2 = (const float*)d_in[5];
    const float* eb2 = (const float*)d_in[6];
    const float* eng = (const float*)d_in[7];
    const float* enb = (const float*)d_in[8];
    const float* aw  = (const float*)d_in[9];
    const float* ab  = (const float*)d_in[10];
    const float* evw = (const float*)d_in[11];
    const float* evb = (const float*)d_in[12];
    const float* ow1 = (const float*)d_in[13];
    const float* ob1 = (const float*)d_in[14];
    const float* ow2 = (const float*)d_in[15];
    const float* ob2 = (const float*)d_in[16];
    const float* nng = (const float*)d_in[17];
    const float* nnb = (const float*)d_in[18];

    float* out = (float*)d_out;
    float* n_out = out;                        // (N, 256)
    float* e_out = out + (size_t)NN * 256;     // (E, 128)

    const int SMEM4 = (64 * 256 + 16 * 256 + 64) * 4;
    cudaFuncSetAttribute(k1_edge_mma, cudaFuncAttributeMaxDynamicSharedMemorySize, SMEM_K1);
    cudaFuncSetAttribute(k4_node, cudaFuncAttributeMaxDynamicSharedMemorySize, SMEM4);

    k_prep<<<768, 256>>>(ew1, ew2);
    k0_node_prep<<<(NN + 7) / 8, 256>>>(nf, aw);
    k1_edge_mma<<<TILES, 256, SMEM_K1>>>(nf, ef, ei, eb1, eb2, eng, enb, aw, ab, e_out);
    k2_exp<<<(EE + 255) / 256, 256>>>(ei);
    k3_scatter<<<EE / 2, 256>>>(ei, e_out);
    k4_node<<<(NN + 63) / 64, 256, SMEM4>>>(nf, evw, evb, ow1, ob1, ow2, ob2, nng, nnb, n_out);
}

// round 11
// speedup vs baseline: 2.1143x; 1.8391x over previous
#include <cuda_runtime.h>
#include <cuda_bf16.h>
#include <cuda_fp16.h>
#include <cstdint>

#define NN 25000
#define EE 400000
#define TILES64 (EE / 64)   // 6250

typedef unsigned long long ull;

// ---- scratch (static device globals; no allocation) ----
__device__ float g_node_score[NN];
__device__ int   g_segmax[NN];
__device__ float g_se[NN];
__device__ float g_agg[(size_t)NN * 128];
__device__ float g_scores[EE];
__device__ float g_ex[EE];
// transposed fp16 weights, K-major [N][K]
__device__ __half g_w1t16[256 * 640];
__device__ __half g_w2t16[128 * 256];

// ---- generic helpers ----
__device__ __forceinline__ ull pk(float lo, float hi) {
    ull r; asm("mov.b64 %0, {%1,%2};" : "=l"(r) : "f"(lo), "f"(hi)); return r;
}
__device__ __forceinline__ float2 upk(ull v) {
    float2 r; asm("mov.b64 {%0,%1}, %2;" : "=f"(r.x), "=f"(r.y) : "l"(v)); return r;
}
__device__ __forceinline__ void fma2(ull& d, ull a, ull b) {
    asm("fma.rn.f32x2 %0, %1, %2, %0;" : "+l"(d) : "l"(a), "l"(b));
}
__device__ __forceinline__ float wred(float v) {
#pragma unroll
    for (int o = 16; o; o >>= 1) v += __shfl_xor_sync(0xffffffffu, v, o);
    return v;
}
__device__ __forceinline__ int f2o(float f) { int i = __float_as_int(f); return i >= 0 ? i : i ^ 0x7fffffff; }
__device__ __forceinline__ float o2f(int i) { return __int_as_float(i >= 0 ? i : i ^ 0x7fffffff); }
__device__ __forceinline__ uint32_t smem_u32(const void* p) {
    uint32_t a; asm("{ .reg .u64 t; cvta.to.shared.u64 t, %1; cvt.u32.u64 %0, t; }" : "=r"(a) : "l"(p));
    return a;
}
__device__ __forceinline__ uint32_t h2u(__half2 h) { return *(uint32_t*)&h; }

// warp-level fp16 MMA (sm_80+ baseline PTX; valid on plain sm_100 target)
__device__ __forceinline__ void mma16816(float* d, const uint32_t* a, uint32_t b0, uint32_t b1) {
    asm volatile(
        "mma.sync.aligned.m16n8k16.row.col.f32.f16.f16.f32 "
        "{%0,%1,%2,%3}, {%4,%5,%6,%7}, {%8,%9}, {%0,%1,%2,%3};"
        : "+f"(d[0]), "+f"(d[1]), "+f"(d[2]), "+f"(d[3])
        : "r"(a[0]), "r"(a[1]), "r"(a[2]), "r"(a[3]), "r"(b0), "r"(b1));
}

// ldmatrix x4 (sm_75+ baseline)
__device__ __forceinline__ void ldmx4(uint32_t* r, uint32_t addr) {
    asm volatile("ldmatrix.sync.aligned.m8n8.x4.shared.b16 {%0,%1,%2,%3}, [%4];"
                 : "=r"(r[0]), "=r"(r[1]), "=r"(r[2]), "=r"(r[3]) : "r"(addr));
}

// ---------------- prep: transpose fp16 weights ----------------
__global__ void k_prep(const float* __restrict__ ew1, const float* __restrict__ ew2) {
    int i = blockIdx.x * 256 + threadIdx.x;
    if (i < 256 * 640) {
        int n = i / 640, k = i - n * 640;
        g_w1t16[i] = __float2half_rn(ew1[(size_t)k * 256 + n]);
    } else {
        int j = i - 256 * 640;
        if (j < 128 * 256) {
            int n = j / 256, k = j - n * 256;
            g_w2t16[j] = __float2half_rn(ew2[(size_t)k * 128 + n]);
        }
    }
}

// ---------------- K0: per-node attention-score part + scratch init ----------------
__global__ void k0_node_prep(const float* __restrict__ nf, const float* __restrict__ aw) {
    int node = blockIdx.x * 8 + (threadIdx.x >> 5);
    int lane = threadIdx.x & 31;
    if (node >= NN) return;
    const float* row = nf + (size_t)node * 256;
    float s = 0.f;
#pragma unroll
    for (int c = lane; c < 256; c += 32) {
        const float4 a = *(const float4*)(aw + c * 4);
        s += row[c] * (a.x + a.y + a.z + a.w);
    }
    s = wred(s);
    if (lane == 0) {
        g_node_score[node] = s * 0.25f;
        g_segmax[node] = (int)0x80000000;
        g_se[node] = 0.f;
    }
    float* ag = g_agg + (size_t)node * 128;
    for (int c = lane; c < 128; c += 32) ag[c] = 0.f;
}

// ---------------- K1: 64-edge tiles, 2-pass fp16 split, occ=2 ----------------
// SMEM (bytes), rows padded to 72 fp16 (144B = 9x16B granules, conflict-free):
//  0:     sidx[64] | 256: didx[64]
//  1024:  A hi [64][72]   (9216)      (also X fp32 [64][132] = 33792 in epilogue2)
//  10240: A lo [64][72]   (9216)
//  19456: B    [128][72]  (18432)
//  37888: H: 4 K-chunks x ([64][72] hi + [64][72] lo) = 4*18432 = 73728 -> total 111616
#define OFF_AH 1024
#define OFF_AL 10240
#define OFF_B  19456
#define OFF_H  37888
#define OFF_X  1024
#define SMEM_K1 111616

// 2-pass split MMA over one 64-K chunk: acc += Ah*B + Al*B
__device__ __forceinline__ void mma_chunk2(float acc[2][4][4],
                                           uint32_t shAH, uint32_t shAL, uint32_t shB) {
#pragma unroll
    for (int ks = 0; ks < 4; ks++) {
        const uint32_t kb2 = ks * 32;  // k bytes
        uint32_t Ah[2][4], Al[2][4];
#pragma unroll
        for (int mt = 0; mt < 2; mt++) {
            ldmx4(Ah[mt], shAH + mt * 2304 + kb2);
            ldmx4(Al[mt], shAL + mt * 2304 + kb2);
        }
#pragma unroll
        for (int ntp = 0; ntp < 2; ntp++) {
            uint32_t b[4];
            ldmx4(b, shB + ntp * 2304 + kb2);
#pragma unroll
            for (int hf = 0; hf < 2; hf++) {
                const int nt = ntp * 2 + hf;
                uint32_t b0 = b[hf * 2], b1 = b[hf * 2 + 1];
                mma16816(acc[0][nt], Ah[0], b0, b1);
                mma16816(acc[1][nt], Ah[1], b0, b1);
                mma16816(acc[0][nt], Al[0], b0, b1);
                mma16816(acc[1][nt], Al[1], b0, b1);
            }
        }
    }
}

__global__ __launch_bounds__(256, 2) void k1_edge_mma(
    const float* __restrict__ nf, const float* __restrict__ ef, const int* __restrict__ ei,
    const float* __restrict__ eb1, const float* __restrict__ eb2,
    const float* __restrict__ eng, const float* __restrict__ enb,
    const float* __restrict__ aw, const float* __restrict__ ab,
    float* __restrict__ e_out) {
    extern __shared__ char smb[];
    int* sidx = (int*)smb;
    int* didx = (int*)(smb + 256);
    const int tid = threadIdx.x;
    const int wid = tid >> 5, lane = tid & 31;
    const int wm = wid >> 2, wn = wid & 3;
    const int m0 = wm * 32;
    const int qr = lane >> 2;         // 0..7
    const int qc = (lane & 3) * 2;    // 0,2,4,6
    const int e0 = blockIdx.x * 64;

    if (tid < 64) sidx[tid] = ei[e0 + tid];
    else if (tid < 128) didx[tid - 64] = ei[EE + e0 + tid - 64];
    __syncthreads();

    // per-lane ldmatrix base addresses (same lane mapping as the passing R10 kernel)
    const uint32_t sbase = smem_u32(smb);
    const int mrow = (lane & 7) + (((lane >> 3) & 1) << 3);
    const uint32_t aOff = (uint32_t)((m0 + mrow) * 144 + ((lane >> 4) << 4));
    const int brow = (lane & 7) + ((lane >> 4) << 3);
    const uint32_t bOff = (uint32_t)((wn * 32 + brow) * 144 + (((lane >> 3) & 1) << 4));
    const uint32_t shAH = sbase + OFF_AH + aOff;
    const uint32_t shAL = sbase + OFF_AL + aOff;
    const uint32_t shB  = sbase + OFF_B + bOff;

    // producer prefetch registers
    float4 pfA[4];  // 16 floats: A row slice
    uint4  pfW[4];  // 64 B: B row slice
    const int arow = tid >> 2, akc = (tid & 3) * 16;   // A: 64 rows x (4 thr x 16 floats)
    const int wrow = tid >> 1, wkc = (tid & 1) * 32;   // B: 128 rows x (2 thr x 32 halfs)

    auto ldA = [&](int c) {
        const int kg = c * 64 + akc;
        const float* base;
        if (kg < 256)      base = nf + (size_t)sidx[arow] * 256 + kg;
        else if (kg < 512) base = nf + (size_t)didx[arow] * 256 + (kg - 256);
        else               base = ef + (size_t)(e0 + arow) * 128 + (kg - 512);
#pragma unroll
        for (int g = 0; g < 4; g++) pfA[g] = *(const float4*)(base + g * 4);
    };
    auto ldW1 = [&](int h, int c) {
        const __half* src = g_w1t16 + (size_t)(h * 128 + wrow) * 640 + c * 64 + wkc;
#pragma unroll
        for (int g = 0; g < 4; g++) pfW[g] = *(const uint4*)(src + g * 8);
    };
    auto ldW2 = [&](int c) {
        const __half* src = g_w2t16 + (size_t)wrow * 256 + c * 64 + wkc;
#pragma unroll
        for (int g = 0; g < 4; g++) pfW[g] = *(const uint4*)(src + g * 8);
    };
    auto stA = [&]() {
        uint32_t hv[8], lv[8];
#pragma unroll
        for (int g = 0; g < 4; g++) {
            float4 v = pfA[g];
            __half2 h0 = __floats2half2_rn(v.x, v.y);
            __half2 h1 = __floats2half2_rn(v.z, v.w);
            float r0 = v.x - __low2float(h0), r1 = v.y - __high2float(h0);
            float r2 = v.z - __low2float(h1), r3 = v.w - __high2float(h1);
            hv[g * 2] = h2u(h0); hv[g * 2 + 1] = h2u(h1);
            lv[g * 2] = h2u(__floats2half2_rn(r0, r1));
            lv[g * 2 + 1] = h2u(__floats2half2_rn(r2, r3));
        }
        const uint32_t off = (uint32_t)(arow * 144 + akc * 2);
        *(uint4*)(smb + OFF_AH + off)      = make_uint4(hv[0], hv[1], hv[2], hv[3]);
        *(uint4*)(smb + OFF_AH + off + 16) = make_uint4(hv[4], hv[5], hv[6], hv[7]);
        *(uint4*)(smb + OFF_AL + off)      = make_uint4(lv[0], lv[1], lv[2], lv[3]);
        *(uint4*)(smb + OFF_AL + off + 16) = make_uint4(lv[4], lv[5], lv[6], lv[7]);
    };
    auto stW = [&]() {
        char* dst = smb + OFF_B + wrow * 144 + wkc * 2;
#pragma unroll
        for (int g = 0; g < 4; g++) *(uint4*)(dst + g * 16) = pfW[g];
    };

    float acc[2][4][4];
#pragma unroll
    for (int mt = 0; mt < 2; mt++)
#pragma unroll
        for (int nt = 0; nt < 4; nt++)
#pragma unroll
            for (int q = 0; q < 4; q++) acc[mt][nt][q] = 0.f;

    // ========= phase 1: 20 pipelined chunks (2 N-halves x 10 K-chunks) =========
    ldA(0); ldW1(0, 0);
#pragma unroll 1
    for (int st = 0; st < 20; st++) {
        const int h = st / 10, c = st % 10;
        __syncthreads();
        stA(); stW();
        __syncthreads();
        if (st < 19) { ldA((st + 1) % 10); ldW1((st + 1) / 10, (st + 1) % 10); }
        else ldW2(0);
        mma_chunk2(acc, shAH, shAL, shB);
        if (c == 9) {
            // epilogue 1: bias + relu + fp16-split -> H chunk
            const int chunk = h * 2 + (wn >> 1);
            char* Hh = smb + OFF_H + chunk * 18432;
            char* Hl = Hh + 9216;
#pragma unroll
            for (int mt = 0; mt < 2; mt++)
#pragma unroll
                for (int nt = 0; nt < 4; nt++) {
                    const int gcol = h * 128 + wn * 32 + nt * 8 + qc;
                    const float b0v = eb1[gcol], b1v = eb1[gcol + 1];
                    const int row = m0 + mt * 16 + qr;
                    const int colc = (wn & 1) * 32 + nt * 8 + qc;
                    float f0 = fmaxf(acc[mt][nt][0] + b0v, 0.f);
                    float f1 = fmaxf(acc[mt][nt][1] + b1v, 0.f);
                    __half2 u = __floats2half2_rn(f0, f1);
                    *(uint32_t*)(Hh + row * 144 + colc * 2) = h2u(u);
                    *(uint32_t*)(Hl + row * 144 + colc * 2) =
                        h2u(__floats2half2_rn(f0 - __low2float(u), f1 - __high2float(u)));
                    float f2 = fmaxf(acc[mt][nt][2] + b0v, 0.f);
                    float f3 = fmaxf(acc[mt][nt][3] + b1v, 0.f);
                    __half2 u2 = __floats2half2_rn(f2, f3);
                    *(uint32_t*)(Hh + (row + 8) * 144 + colc * 2) = h2u(u2);
                    *(uint32_t*)(Hl + (row + 8) * 144 + colc * 2) =
                        h2u(__floats2half2_rn(f2 - __low2float(u2), f3 - __high2float(u2)));
                }
#pragma unroll
            for (int mt = 0; mt < 2; mt++)
#pragma unroll
                for (int nt = 0; nt < 4; nt++)
#pragma unroll
                    for (int q = 0; q < 4; q++) acc[mt][nt][q] = 0.f;
        }
    }

    // ========= phase 2: H(64x256) @ W2(256x128), 4 pipelined chunks =========
#pragma unroll 1
    for (int c2 = 0; c2 < 4; c2++) {
        __syncthreads();
        stW();
        __syncthreads();
        if (c2 < 3) ldW2(c2 + 1);
        const uint32_t shH = sbase + OFF_H + c2 * 18432 + aOff;
        mma_chunk2(acc, shH, shH + 9216, shB);
    }

    // ========= epilogue 2: bias + residual -> X, LN, score =========
    __syncthreads();
    float* X = (float*)(smb + OFF_X);
#pragma unroll
    for (int mt = 0; mt < 2; mt++)
#pragma unroll
        for (int nt = 0; nt < 4; nt++) {
            const int col = wn * 32 + nt * 8 + qc;
            const float b0v = eb2[col], b1v = eb2[col + 1];
            const int row = m0 + mt * 16 + qr;
            float2 v0, v1;
            v0.x = acc[mt][nt][0] + b0v + ef[(size_t)(e0 + row) * 128 + col];
            v0.y = acc[mt][nt][1] + b1v + ef[(size_t)(e0 + row) * 128 + col + 1];
            v1.x = acc[mt][nt][2] + b0v + ef[(size_t)(e0 + row + 8) * 128 + col];
            v1.y = acc[mt][nt][3] + b1v + ef[(size_t)(e0 + row + 8) * 128 + col + 1];
            *(float2*)(X + row * 132 + col) = v0;
            *(float2*)(X + (row + 8) * 132 + col) = v1;
        }
    __syncthreads();

    const float abm = 0.25f * (ab[0] + ab[1] + ab[2] + ab[3]);
    const int c4 = lane * 4;
    const float4 g4 = *(const float4*)(eng + c4);
    const float4 b4 = *(const float4*)(enb + c4);
    float4 t0 = *(const float4*)(aw + (256 + c4) * 4);
    float4 t1 = *(const float4*)(aw + (256 + c4 + 1) * 4);
    float4 t2 = *(const float4*)(aw + (256 + c4 + 2) * 4);
    float4 t3 = *(const float4*)(aw + (256 + c4 + 3) * 4);
    const float wa0 = t0.x + t0.y + t0.z + t0.w;
    const float wa1 = t1.x + t1.y + t1.z + t1.w;
    const float wa2 = t2.x + t2.y + t2.z + t2.w;
    const float wa3 = t3.x + t3.y + t3.z + t3.w;
#pragma unroll 1
    for (int rr = 0; rr < 8; rr++) {
        const int row = wid * 8 + rr;
        float4 v = *(const float4*)(X + row * 132 + c4);
        float mean = wred(v.x + v.y + v.z + v.w) * (1.f / 128.f);
        float dx = v.x - mean, dy = v.y - mean, dz = v.z - mean, dw = v.w - mean;
        float var = wred(dx * dx + dy * dy + dz * dz + dw * dw) * (1.f / 128.f);
        float rstd = rsqrtf(var + 1e-5f);
        float4 y;
        y.x = dx * rstd * g4.x + b4.x;
        y.y = dy * rstd * g4.y + b4.y;
        y.z = dz * rstd * g4.z + b4.z;
        y.w = dw * rstd * g4.w + b4.w;
        *(float4*)(e_out + (size_t)(e0 + row) * 128 + c4) = y;
        float sp = wred(y.x * wa0 + y.y * wa1 + y.z * wa2 + y.w * wa3);
        if (lane == 0) {
            int dd = didx[row];
            float sc = sp * 0.25f + g_node_score[dd] + abm;
            g_scores[e0 + row] = sc;
            atomicMax(&g_segmax[dd], f2o(sc));
        }
    }
}

// ---------------- K2: ex = exp(score - segmax[dst]); se[dst] += ex ----------------
__global__ void k2_exp(const int* __restrict__ ei) {
    int e = blockIdx.x * 256 + threadIdx.x;
    if (e >= EE) return;
    int d = ei[EE + e];
    float ex = expf(g_scores[e] - o2f(g_segmax[d]));
    g_ex[e] = ex;
    atomicAdd(&g_se[d], ex);
}

// ---------------- K3: agg[dst] += w_e * e_e ----------------
__global__ void k3_scatter(const int* __restrict__ ei, const float* __restrict__ e_feat) {
    int e = blockIdx.x * 2 + (threadIdx.x >> 7);
    int c = threadIdx.x & 127;
    int d = ei[EE + e];
    float w = g_ex[e] / (g_se[d] + 1e-6f);
    atomicAdd(&g_agg[(size_t)d * 128 + c], w * e_feat[(size_t)e * 128 + c]);
}

// ---------------- K4: node update (3 fused GEMMs + residual + LN), f32x2 ----------------
template <int KDIM, int NCOLS>
__device__ __forceinline__ void gemm_smem(const float* Xs, int ldx,
                                          const float* __restrict__ Bg,
                                          float* Bs, ull* acc, int tid) {
    constexpr int NP = NCOLS / 32;
    const int tx = tid & 15, ty = tid >> 4;
#pragma unroll 1
    for (int k0 = 0; k0 < KDIM; k0 += 16) {
        __syncthreads();
        constexpr int NF4 = 16 * NCOLS / 4;
#pragma unroll
        for (int j = 0; j < NF4 / 256; j++) {
            int f = tid + j * 256;
            int rr = f / (NCOLS / 4);
            int cc = (f - rr * (NCOLS / 4)) * 4;
            *(float4*)(Bs + rr * NCOLS + cc) = *(const float4*)(Bg + (size_t)(k0 + rr) * NCOLS + cc);
        }
        __syncthreads();
#pragma unroll
        for (int kk = 0; kk < 16; kk++) {
            ull aa[4];
#pragma unroll
            for (int i = 0; i < 4; i++) { float a = Xs[(ty * 4 + i) * ldx + k0 + kk]; aa[i] = pk(a, a); }
#pragma unroll
            for (int p = 0; p < NP; p++) {
                ull bb = *(const ull*)(Bs + kk * NCOLS + (tx + 16 * p) * 2);
#pragma unroll
                for (int i = 0; i < 4; i++) fma2(acc[i * NP + p], aa[i], bb);
            }
        }
    }
    __syncthreads();
}

__global__ __launch_bounds__(256, 2) void k4_node(
    const float* __restrict__ nf,
    const float* __restrict__ evw, const float* __restrict__ evb,
    const float* __restrict__ ow1, const float* __restrict__ ob1,
    const float* __restrict__ ow2, const float* __restrict__ ob2,
    const float* __restrict__ nng, const float* __restrict__ nnb,
    float* __restrict__ n_out) {
    extern __shared__ float sm[];
    float* X  = sm;              // 64*256
    float* Bs = X + 64 * 256;    // 16*256
    float* sw = Bs + 16 * 256;   // 64
    const int tid = threadIdx.x;
    const int tx = tid & 15, ty = tid >> 4;
    const int n0 = blockIdx.x * 64;
#pragma unroll
    for (int j = 0; j < 8; j++) {
        int f = tid + j * 256;
        int rr = f >> 5; int cc = (f & 31) * 4;
        float4 v = make_float4(0.f, 0.f, 0.f, 0.f);
        if (n0 + rr < NN) v = *(const float4*)(g_agg + (size_t)(n0 + rr) * 128 + cc);
        *(float4*)(X + rr * 128 + cc) = v;
    }
    if (tid < 64) {
        int nn2 = n0 + tid;
        float se = (nn2 < NN) ? g_se[nn2] : 0.f;
        sw[tid] = se / (se + 1e-6f);
    }
    ull acc[32];
#pragma unroll
    for (int i = 0; i < 32; i++) acc[i] = 0ull;
    gemm_smem<128, 256>(X, 128, evw, Bs, acc, tid);
#pragma unroll
    for (int i = 0; i < 4; i++) {
        int rr = ty * 4 + i;
        float s = sw[rr];
#pragma unroll
        for (int p = 0; p < 8; p++) {
            int c0 = (tx + 16 * p) * 2;
            float2 v = upk(acc[i * 8 + p]);
            v.x += s * evb[c0];
            v.y += s * evb[c0 + 1];
            *(float2*)(X + rr * 256 + c0) = v;
        }
    }
#pragma unroll
    for (int i = 0; i < 32; i++) acc[i] = 0ull;
    gemm_smem<256, 256>(X, 256, ow1, Bs, acc, tid);
#pragma unroll
    for (int i = 0; i < 4; i++) {
        int rr = ty * 4 + i;
#pragma unroll
        for (int p = 0; p < 8; p++) {
            int c0 = (tx + 16 * p) * 2;
            float2 v = upk(acc[i * 8 + p]);
            v.x = fmaxf(v.x + ob1[c0], 0.f);
            v.y = fmaxf(v.y + ob1[c0 + 1], 0.f);
            *(float2*)(X + rr * 256 + c0) = v;
        }
    }
#pragma unroll
    for (int i = 0; i < 32; i++) acc[i] = 0ull;
    gemm_smem<256, 256>(X, 256, ow2, Bs, acc, tid);
#pragma unroll
    for (int i = 0; i < 4; i++) {
        int rr = ty * 4 + i;
        int row = n0 + rr;
#pragma unroll
        for (int p = 0; p < 8; p++) {
            int c0 = (tx + 16 * p) * 2;
            float2 v = upk(acc[i * 8 + p]);
            v.x += ob2[c0];
            v.y += ob2[c0 + 1];
            if (row < NN) {
                v.x += nf[(size_t)row * 256 + c0];
                v.y += nf[(size_t)row * 256 + c0 + 1];
            }
            *(float2*)(X + rr * 256 + c0) = v;
        }
    }
    __syncthreads();
    const int wp = tid >> 5, lane = tid & 31;
    const int cb = lane * 8;
    float4 g0 = *(const float4*)(nng + cb), g1 = *(const float4*)(nng + cb + 4);
    float4 h0 = *(const float4*)(nnb + cb), h1 = *(const float4*)(nnb + cb + 4);
#pragma unroll 1
    for (int rr = 0; rr < 8; rr++) {
        int rrow = wp * 8 + rr;
        int row = n0 + rrow;
        float4 v0 = *(const float4*)(X + rrow * 256 + cb);
        float4 v1 = *(const float4*)(X + rrow * 256 + cb + 4);
        float mean = wred(v0.x + v0.y + v0.z + v0.w + v1.x + v1.y + v1.z + v1.w) * (1.f / 256.f);
        float d0x = v0.x - mean, d0y = v0.y - mean, d0z = v0.z - mean, d0w = v0.w - mean;
        float d1x = v1.x - mean, d1y = v1.y - mean, d1z = v1.z - mean, d1w = v1.w - mean;
        float var = wred(d0x * d0x + d0y * d0y + d0z * d0z + d0w * d0w +
                         d1x * d1x + d1y * d1y + d1z * d1z + d1w * d1w) * (1.f / 256.f);
        float rstd = rsqrtf(var + 1e-5f);
        if (row < NN) {
            float4 y0, y1;
            y0.x = d0x * rstd * g0.x + h0.x; y0.y = d0y * rstd * g0.y + h0.y;
            y0.z = d0z * rstd * g0.z + h0.z; y0.w = d0w * rstd * g0.w + h0.w;
            y1.x = d1x * rstd * g1.x + h1.x; y1.y = d1y * rstd * g1.y + h1.y;
            y1.z = d1z * rstd * g1.z + h1.z; y1.w = d1w * rstd * g1.w + h1.w;
            *(float4*)(n_out + (size_t)row * 256 + cb) = y0;
            *(float4*)(n_out + (size_t)row * 256 + cb + 4) = y1;
        }
    }
}

// ---------------- launch ----------------
extern "C" void kernel_launch(void* const* d_in, const int* in_sizes, int n_in,
                              void* d_out, int out_size) {
    const float* nf  = (const float*)d_in[0];
    const float* ef  = (const float*)d_in[1];
    const int*   ei  = (const int*)d_in[2];
    const float* ew1 = (const float*)d_in[3];
    const float* eb1 = (const float*)d_in[4];
    const float* ew2 = (const float*)d_in[5];
    const float* eb2 = (const float*)d_in[6];
    const float* eng = (const float*)d_in[7];
    const float* enb = (const float*)d_in[8];
    const float* aw  = (const float*)d_in[9];
    const float* ab  = (const float*)d_in[10];
    const float* evw = (const float*)d_in[11];
    const float* evb = (const float*)d_in[12];
    const float* ow1 = (const float*)d_in[13];
    const float* ob1 = (const float*)d_in[14];
    const float* ow2 = (const float*)d_in[15];
    const float* ob2 = (const float*)d_in[16];
    const float* nng = (const float*)d_in[17];
    const float* nnb = (const float*)d_in[18];

    float* out = (float*)d_out;
    float* n_out = out;                        // (N, 256)
    float* e_out = out + (size_t)NN * 256;     // (E, 128)

    const int SMEM4 = (64 * 256 + 16 * 256 + 64) * 4;
    cudaFuncSetAttribute(k1_edge_mma, cudaFuncAttributeMaxDynamicSharedMemorySize, SMEM_K1);
    cudaFuncSetAttribute(k4_node, cudaFuncAttributeMaxDynamicSharedMemorySize, SMEM4);

    k_prep<<<768, 256>>>(ew1, ew2);
    k0_node_prep<<<(NN + 7) / 8, 256>>>(nf, aw);
    k1_edge_mma<<<TILES64, 256, SMEM_K1>>>(nf, ef, ei, eb1, eb2, eng, enb, aw, ab, e_out);
    k2_exp<<<(EE + 255) / 256, 256>>>(ei);
    k3_scatter<<<EE / 2, 256>>>(ei, e_out);
    k4_node<<<(NN + 63) / 64, 256, SMEM4>>>(nf, evw, evb, ow1, ob1, ow2, ob2, nng, nnb, n_out);
}

// round 13
// speedup vs baseline: 2.4387x; 1.1534x over previous
#include <cuda_runtime.h>
#include <cuda_bf16.h>
#include <cuda_fp16.h>
#include <cstdint>

#define NN 25000
#define EE 400000
#define TILES64 (EE / 64)   // 6250

typedef unsigned long long ull;

// ---- scratch (static device globals; no allocation) ----
__device__ float g_node_score[NN];
__device__ int   g_segmax[NN];
__device__ float g_se[NN];
__device__ float g_agg[(size_t)NN * 128];
__device__ float g_scores[EE];
__device__ float g_ex[EE];
// transposed fp16 weights, K-major [N][K]
__device__ __half g_w1t16[256 * 640];
__device__ __half g_w2t16[128 * 256];

// ---- generic helpers ----
__device__ __forceinline__ ull pk(float lo, float hi) {
    ull r; asm("mov.b64 %0, {%1,%2};" : "=l"(r) : "f"(lo), "f"(hi)); return r;
}
__device__ __forceinline__ float2 upk(ull v) {
    float2 r; asm("mov.b64 {%0,%1}, %2;" : "=f"(r.x), "=f"(r.y) : "l"(v)); return r;
}
__device__ __forceinline__ void fma2(ull& d, ull a, ull b) {
    asm("fma.rn.f32x2 %0, %1, %2, %0;" : "+l"(d) : "l"(a), "l"(b));
}
__device__ __forceinline__ float wred(float v) {
#pragma unroll
    for (int o = 16; o; o >>= 1) v += __shfl_xor_sync(0xffffffffu, v, o);
    return v;
}
__device__ __forceinline__ int f2o(float f) { int i = __float_as_int(f); return i >= 0 ? i : i ^ 0x7fffffff; }
__device__ __forceinline__ float o2f(int i) { return __int_as_float(i >= 0 ? i : i ^ 0x7fffffff); }
__device__ __forceinline__ uint32_t smem_u32(const void* p) {
    uint32_t a; asm("{ .reg .u64 t; cvta.to.shared.u64 t, %1; cvt.u32.u64 %0, t; }" : "=r"(a) : "l"(p));
    return a;
}
__device__ __forceinline__ uint32_t h2u(__half2 h) { return *(uint32_t*)&h; }

// warp-level fp16 MMA (sm_80+ baseline PTX; valid on plain sm_100 target)
__device__ __forceinline__ void mma16816(float* d, const uint32_t* a, uint32_t b0, uint32_t b1) {
    asm volatile(
        "mma.sync.aligned.m16n8k16.row.col.f32.f16.f16.f32 "
        "{%0,%1,%2,%3}, {%4,%5,%6,%7}, {%8,%9}, {%0,%1,%2,%3};"
        : "+f"(d[0]), "+f"(d[1]), "+f"(d[2]), "+f"(d[3])
        : "r"(a[0]), "r"(a[1]), "r"(a[2]), "r"(a[3]), "r"(b0), "r"(b1));
}

// ldmatrix x4 (sm_75+ baseline)
__device__ __forceinline__ void ldmx4(uint32_t* r, uint32_t addr) {
    asm volatile("ldmatrix.sync.aligned.m8n8.x4.shared.b16 {%0,%1,%2,%3}, [%4];"
                 : "=r"(r[0]), "=r"(r[1]), "=r"(r[2]), "=r"(r[3]) : "r"(addr));
}

// ---------------- prep: transpose fp16 weights ----------------
__global__ void k_prep(const float* __restrict__ ew1, const float* __restrict__ ew2) {
    int i = blockIdx.x * 256 + threadIdx.x;
    if (i < 256 * 640) {
        int n = i / 640, k = i - n * 640;
        g_w1t16[i] = __float2half_rn(ew1[(size_t)k * 256 + n]);
    } else {
        int j = i - 256 * 640;
        if (j < 128 * 256) {
            int n = j / 256, k = j - n * 256;
            g_w2t16[j] = __float2half_rn(ew2[(size_t)k * 128 + n]);
        }
    }
}

// ---------------- K0: per-node attention-score part + scratch init ----------------
__global__ void k0_node_prep(const float* __restrict__ nf, const float* __restrict__ aw) {
    int node = blockIdx.x * 8 + (threadIdx.x >> 5);
    int lane = threadIdx.x & 31;
    if (node >= NN) return;
    const float* row = nf + (size_t)node * 256;
    float s = 0.f;
#pragma unroll
    for (int c = lane; c < 256; c += 32) {
        const float4 a = *(const float4*)(aw + c * 4);
        s += row[c] * (a.x + a.y + a.z + a.w);
    }
    s = wred(s);
    if (lane == 0) {
        g_node_score[node] = s * 0.25f;
        g_segmax[node] = (int)0x80000000;
        g_se[node] = 0.f;
    }
    float* ag = g_agg + (size_t)node * 128;
    for (int c = lane; c < 128; c += 32) ag[c] = 0.f;
}

// ---------------- K1: 64-edge tiles, single-pass fp16, occ=2 ----------------
// SMEM (bytes), rows padded to 72 fp16 (144B = 9x16B granules, conflict-free):
//  0:     sidx[64] | 256: didx[64]
//  1024:  A    [64][72]   (9216)
//  10240: B    [128][72]  (18432)
//  28672: H: 4 K-chunks x [64][72] = 36864    (also X fp32 [64][132] = 33792 in epilogue2)
//  total 65536
#define OFF_A  1024
#define OFF_B  10240
#define OFF_H  28672
#define OFF_X  28672
#define SMEM_K1 65536

// single-pass MMA over one 64-K chunk: acc += A*B
__device__ __forceinline__ void mma_chunk1(float acc[2][4][4], uint32_t shA, uint32_t shB) {
#pragma unroll
    for (int ks = 0; ks < 4; ks++) {
        const uint32_t kb2 = ks * 32;  // k bytes
        uint32_t Aa[2][4];
        ldmx4(Aa[0], shA + kb2);
        ldmx4(Aa[1], shA + 2304 + kb2);
#pragma unroll
        for (int ntp = 0; ntp < 2; ntp++) {
            uint32_t b[4];
            ldmx4(b, shB + ntp * 2304 + kb2);
#pragma unroll
            for (int hf = 0; hf < 2; hf++) {
                const int nt = ntp * 2 + hf;
                mma16816(acc[0][nt], Aa[0], b[hf * 2], b[hf * 2 + 1]);
                mma16816(acc[1][nt], Aa[1], b[hf * 2], b[hf * 2 + 1]);
            }
        }
    }
}

__global__ __launch_bounds__(256, 2) void k1_edge_mma(
    const float* __restrict__ nf, const float* __restrict__ ef, const int* __restrict__ ei,
    const float* __restrict__ eb1, const float* __restrict__ eb2,
    const float* __restrict__ eng, const float* __restrict__ enb,
    const float* __restrict__ aw, const float* __restrict__ ab,
    float* __restrict__ e_out) {
    extern __shared__ char smb[];
    int* sidx = (int*)smb;
    int* didx = (int*)(smb + 256);
    const int tid = threadIdx.x;
    const int wid = tid >> 5, lane = tid & 31;
    const int wm = wid >> 2, wn = wid & 3;
    const int m0 = wm * 32;
    const int qr = lane >> 2;         // 0..7
    const int qc = (lane & 3) * 2;    // 0,2,4,6
    const int e0 = blockIdx.x * 64;

    if (tid < 64) sidx[tid] = ei[e0 + tid];
    else if (tid < 128) didx[tid - 64] = ei[EE + e0 + tid - 64];
    __syncthreads();

    // per-lane ldmatrix base addresses (same lane mapping as the passing R11 kernel)
    const uint32_t sbase = smem_u32(smb);
    const int mrow = (lane & 7) + (((lane >> 3) & 1) << 3);
    const uint32_t aOff = (uint32_t)((m0 + mrow) * 144 + ((lane >> 4) << 4));
    const int brow = (lane & 7) + ((lane >> 4) << 3);
    const uint32_t bOff = (uint32_t)((wn * 32 + brow) * 144 + (((lane >> 3) & 1) << 4));
    const uint32_t shA = sbase + OFF_A + aOff;
    const uint32_t shB = sbase + OFF_B + bOff;

    // producer prefetch registers
    float4 pfA[4];  // 16 floats: A row slice
    uint4  pfW[4];  // 64 B: B row slice
    const int arow = tid >> 2, akc = (tid & 3) * 16;   // A: 64 rows x (4 thr x 16 floats)
    const int wrow = tid >> 1, wkc = (tid & 1) * 32;   // B: 128 rows x (2 thr x 32 halfs)

    auto ldA = [&](int c) {
        const int kg = c * 64 + akc;
        const float* base;
        if (kg < 256)      base = nf + (size_t)sidx[arow] * 256 + kg;
        else if (kg < 512) base = nf + (size_t)didx[arow] * 256 + (kg - 256);
        else               base = ef + (size_t)(e0 + arow) * 128 + (kg - 512);
#pragma unroll
        for (int g = 0; g < 4; g++) pfA[g] = *(const float4*)(base + g * 4);
    };
    auto ldW1 = [&](int h, int c) {
        const __half* src = g_w1t16 + (size_t)(h * 128 + wrow) * 640 + c * 64 + wkc;
#pragma unroll
        for (int g = 0; g < 4; g++) pfW[g] = *(const uint4*)(src + g * 8);
    };
    auto ldW2 = [&](int c) {
        const __half* src = g_w2t16 + (size_t)wrow * 256 + c * 64 + wkc;
#pragma unroll
        for (int g = 0; g < 4; g++) pfW[g] = *(const uint4*)(src + g * 8);
    };
    auto stA = [&]() {
        uint32_t hv[8];
#pragma unroll
        for (int g = 0; g < 4; g++) {
            float4 v = pfA[g];
            hv[g * 2]     = h2u(__floats2half2_rn(v.x, v.y));
            hv[g * 2 + 1] = h2u(__floats2half2_rn(v.z, v.w));
        }
        const uint32_t off = (uint32_t)(arow * 144 + akc * 2);
        *(uint4*)(smb + OFF_A + off)      = make_uint4(hv[0], hv[1], hv[2], hv[3]);
        *(uint4*)(smb + OFF_A + off + 16) = make_uint4(hv[4], hv[5], hv[6], hv[7]);
    };
    auto stW = [&]() {
        char* dst = smb + OFF_B + wrow * 144 + wkc * 2;
#pragma unroll
        for (int g = 0; g < 4; g++) *(uint4*)(dst + g * 16) = pfW[g];
    };

    float acc[2][4][4];
#pragma unroll
    for (int mt = 0; mt < 2; mt++)
#pragma unroll
        for (int nt = 0; nt < 4; nt++)
#pragma unroll
            for (int q = 0; q < 4; q++) acc[mt][nt][q] = 0.f;

    // ========= phase 1: 20 pipelined chunks (2 N-halves x 10 K-chunks) =========
    ldA(0); ldW1(0, 0);
#pragma unroll 1
    for (int st = 0; st < 20; st++) {
        const int h = st / 10, c = st % 10;
        __syncthreads();
        stA(); stW();
        __syncthreads();
        if (st < 19) { ldA((st + 1) % 10); ldW1((st + 1) / 10, (st + 1) % 10); }
        else ldW2(0);
        mma_chunk1(acc, shA, shB);
        if (c == 9) {
            // epilogue 1: bias + relu + fp16 -> H chunk
            const int chunk = h * 2 + (wn >> 1);
            char* Hh = smb + OFF_H + chunk * 9216;
#pragma unroll
            for (int mt = 0; mt < 2; mt++)
#pragma unroll
                for (int nt = 0; nt < 4; nt++) {
                    const int gcol = h * 128 + wn * 32 + nt * 8 + qc;
                    const float b0v = eb1[gcol], b1v = eb1[gcol + 1];
                    const int row = m0 + mt * 16 + qr;
                    const int colc = (wn & 1) * 32 + nt * 8 + qc;
                    float f0 = fmaxf(acc[mt][nt][0] + b0v, 0.f);
                    float f1 = fmaxf(acc[mt][nt][1] + b1v, 0.f);
                    *(uint32_t*)(Hh + row * 144 + colc * 2) = h2u(__floats2half2_rn(f0, f1));
                    float f2 = fmaxf(acc[mt][nt][2] + b0v, 0.f);
                    float f3 = fmaxf(acc[mt][nt][3] + b1v, 0.f);
                    *(uint32_t*)(Hh + (row + 8) * 144 + colc * 2) = h2u(__floats2half2_rn(f2, f3));
                }
#pragma unroll
            for (int mt = 0; mt < 2; mt++)
#pragma unroll
                for (int nt = 0; nt < 4; nt++)
#pragma unroll
                    for (int q = 0; q < 4; q++) acc[mt][nt][q] = 0.f;
        }
    }

    // ========= phase 2: H(64x256) @ W2(256x128), 4 pipelined chunks =========
#pragma unroll 1
    for (int c2 = 0; c2 < 4; c2++) {
        __syncthreads();
        stW();
        __syncthreads();
        if (c2 < 3) ldW2(c2 + 1);
        const uint32_t shH = sbase + OFF_H + c2 * 9216 + aOff;
        mma_chunk1(acc, shH, shB);
    }

    // ========= epilogue 2: bias + residual -> X, LN, score =========
    __syncthreads();
    float* X = (float*)(smb + OFF_X);
#pragma unroll
    for (int mt = 0; mt < 2; mt++)
#pragma unroll
        for (int nt = 0; nt < 4; nt++) {
            const int col = wn * 32 + nt * 8 + qc;
            const float b0v = eb2[col], b1v = eb2[col + 1];
            const int row = m0 + mt * 16 + qr;
            float2 v0, v1;
            v0.x = acc[mt][nt][0] + b0v + ef[(size_t)(e0 + row) * 128 + col];
            v0.y = acc[mt][nt][1] + b1v + ef[(size_t)(e0 + row) * 128 + col + 1];
            v1.x = acc[mt][nt][2] + b0v + ef[(size_t)(e0 + row + 8) * 128 + col];
            v1.y = acc[mt][nt][3] + b1v + ef[(size_t)(e0 + row + 8) * 128 + col + 1];
            *(float2*)(X + row * 132 + col) = v0;
            *(float2*)(X + (row + 8) * 132 + col) = v1;
        }
    __syncthreads();

    const float abm = 0.25f * (ab[0] + ab[1] + ab[2] + ab[3]);
    const int c4 = lane * 4;
    const float4 g4 = *(const float4*)(eng + c4);
    const float4 b4 = *(const float4*)(enb + c4);
    float4 t0 = *(const float4*)(aw + (256 + c4) * 4);
    float4 t1 = *(const float4*)(aw + (256 + c4 + 1) * 4);
    float4 t2 = *(const float4*)(aw + (256 + c4 + 2) * 4);
    float4 t3 = *(const float4*)(aw + (256 + c4 + 3) * 4);
    const float wa0 = t0.x + t0.y + t0.z + t0.w;
    const float wa1 = t1.x + t1.y + t1.z + t1.w;
    const float wa2 = t2.x + t2.y + t2.z + t2.w;
    const float wa3 = t3.x + t3.y + t3.z + t3.w;
#pragma unroll 1
    for (int rr = 0; rr < 8; rr++) {
        const int row = wid * 8 + rr;
        float4 v = *(const float4*)(X + row * 132 + c4);
        float mean = wred(v.x + v.y + v.z + v.w) * (1.f / 128.f);
        float dx = v.x - mean, dy = v.y - mean, dz = v.z - mean, dw = v.w - mean;
        float var = wred(dx * dx + dy * dy + dz * dz + dw * dw) * (1.f / 128.f);
        float rstd = rsqrtf(var + 1e-5f);
        float4 y;
        y.x = dx * rstd * g4.x + b4.x;
        y.y = dy * rstd * g4.y + b4.y;
        y.z = dz * rstd * g4.z + b4.z;
        y.w = dw * rstd * g4.w + b4.w;
        *(float4*)(e_out + (size_t)(e0 + row) * 128 + c4) = y;
        float sp = wred(y.x * wa0 + y.y * wa1 + y.z * wa2 + y.w * wa3);
        if (lane == 0) {
            int dd = didx[row];
            float sc = sp * 0.25f + g_node_score[dd] + abm;
            g_scores[e0 + row] = sc;
            atomicMax(&g_segmax[dd], f2o(sc));
        }
    }
}

// ---------------- K2: ex = exp(score - segmax[dst]); se[dst] += ex ----------------
__global__ void k2_exp(const int* __restrict__ ei) {
    int e = blockIdx.x * 256 + threadIdx.x;
    if (e >= EE) return;
    int d = ei[EE + e];
    float ex = expf(g_scores[e] - o2f(g_segmax[d]));
    g_ex[e] = ex;
    atomicAdd(&g_se[d], ex);
}

// ---------------- K3: agg[dst] += w_e * e_e ----------------
__global__ void k3_scatter(const int* __restrict__ ei, const float* __restrict__ e_feat) {
    int e = blockIdx.x * 2 + (threadIdx.x >> 7);
    int c = threadIdx.x & 127;
    int d = ei[EE + e];
    float w = g_ex[e] / (g_se[d] + 1e-6f);
    atomicAdd(&g_agg[(size_t)d * 128 + c], w * e_feat[(size_t)e * 128 + c]);
}

// ---------------- K4: node update (3 fused GEMMs + residual + LN), f32x2 ----------------
template <int KDIM, int NCOLS>
__device__ __forceinline__ void gemm_smem(const float* Xs, int ldx,
                                          const float* __restrict__ Bg,
                                          float* Bs, ull* acc, int tid) {
    constexpr int NP = NCOLS / 32;
    const int tx = tid & 15, ty = tid >> 4;
#pragma unroll 1
    for (int k0 = 0; k0 < KDIM; k0 += 16) {
        __syncthreads();
        constexpr int NF4 = 16 * NCOLS / 4;
#pragma unroll
        for (int j = 0; j < NF4 / 256; j++) {
            int f = tid + j * 256;
            int rr = f / (NCOLS / 4);
            int cc = (f - rr * (NCOLS / 4)) * 4;
            *(float4*)(Bs + rr * NCOLS + cc) = *(const float4*)(Bg + (size_t)(k0 + rr) * NCOLS + cc);
        }
        __syncthreads();
#pragma unroll
        for (int kk = 0; kk < 16; kk++) {
            ull aa[4];
#pragma unroll
            for (int i = 0; i < 4; i++) { float a = Xs[(ty * 4 + i) * ldx + k0 + kk]; aa[i] = pk(a, a); }
#pragma unroll
            for (int p = 0; p < NP; p++) {
                ull bb = *(const ull*)(Bs + kk * NCOLS + (tx + 16 * p) * 2);
#pragma unroll
                for (int i = 0; i < 4; i++) fma2(acc[i * NP + p], aa[i], bb);
            }
        }
    }
    __syncthreads();
}

__global__ __launch_bounds__(256, 2) void k4_node(
    const float* __restrict__ nf,
    const float* __restrict__ evw, const float* __restrict__ evb,
    const float* __restrict__ ow1, const float* __restrict__ ob1,
    const float* __restrict__ ow2, const float* __restrict__ ob2,
    const float* __restrict__ nng, const float* __restrict__ nnb,
    float* __restrict__ n_out) {
    extern __shared__ float sm[];
    float* X  = sm;              // 64*256
    float* Bs = X + 64 * 256;    // 16*256
    float* sw = Bs + 16 * 256;   // 64
    const int tid = threadIdx.x;
    const int tx = tid & 15, ty = tid >> 4;
    const int n0 = blockIdx.x * 64;
#pragma unroll
    for (int j = 0; j < 8; j++) {
        int f = tid + j * 256;
        int rr = f >> 5; int cc = (f & 31) * 4;
        float4 v = make_float4(0.f, 0.f, 0.f, 0.f);
        if (n0 + rr < NN) v = *(const float4*)(g_agg + (size_t)(n0 + rr) * 128 + cc);
        *(float4*)(X + rr * 128 + cc) = v;
    }
    if (tid < 64) {
        int nn2 = n0 + tid;
        float se = (nn2 < NN) ? g_se[nn2] : 0.f;
        sw[tid] = se / (se + 1e-6f);
    }
    ull acc[32];
#pragma unroll
    for (int i = 0; i < 32; i++) acc[i] = 0ull;
    gemm_smem<128, 256>(X, 128, evw, Bs, acc, tid);
#pragma unroll
    for (int i = 0; i < 4; i++) {
        int rr = ty * 4 + i;
        float s = sw[rr];
#pragma unroll
        for (int p = 0; p < 8; p++) {
            int c0 = (tx + 16 * p) * 2;
            float2 v = upk(acc[i * 8 + p]);
            v.x += s * evb[c0];
            v.y += s * evb[c0 + 1];
            *(float2*)(X + rr * 256 + c0) = v;
        }
    }
#pragma unroll
    for (int i = 0; i < 32; i++) acc[i] = 0ull;
    gemm_smem<256, 256>(X, 256, ow1, Bs, acc, tid);
#pragma unroll
    for (int i = 0; i < 4; i++) {
        int rr = ty * 4 + i;
#pragma unroll
        for (int p = 0; p < 8; p++) {
            int c0 = (tx + 16 * p) * 2;
            float2 v = upk(acc[i * 8 + p]);
            v.x = fmaxf(v.x + ob1[c0], 0.f);
            v.y = fmaxf(v.y + ob1[c0 + 1], 0.f);
            *(float2*)(X + rr * 256 + c0) = v;
        }
    }
#pragma unroll
    for (int i = 0; i < 32; i++) acc[i] = 0ull;
    gemm_smem<256, 256>(X, 256, ow2, Bs, acc, tid);
#pragma unroll
    for (int i = 0; i < 4; i++) {
        int rr = ty * 4 + i;
        int row = n0 + rr;
#pragma unroll
        for (int p = 0; p < 8; p++) {
            int c0 = (tx + 16 * p) * 2;
            float2 v = upk(acc[i * 8 + p]);
            v.x += ob2[c0];
            v.y += ob2[c0 + 1];
            if (row < NN) {
                v.x += nf[(size_t)row * 256 + c0];
                v.y += nf[(size_t)row * 256 + c0 + 1];
            }
            *(float2*)(X + rr * 256 + c0) = v;
        }
    }
    __syncthreads();
    const int wp = tid >> 5, lane = tid & 31;
    const int cb = lane * 8;
    float4 g0 = *(const float4*)(nng + cb), g1 = *(const float4*)(nng + cb + 4);
    float4 h0 = *(const float4*)(nnb + cb), h1 = *(const float4*)(nnb + cb + 4);
#pragma unroll 1
    for (int rr = 0; rr < 8; rr++) {
        int rrow = wp * 8 + rr;
        int row = n0 + rrow;
        float4 v0 = *(const float4*)(X + rrow * 256 + cb);
        float4 v1 = *(const float4*)(X + rrow * 256 + cb + 4);
        float mean = wred(v0.x + v0.y + v0.z + v0.w + v1.x + v1.y + v1.z + v1.w) * (1.f / 256.f);
        float d0x = v0.x - mean, d0y = v0.y - mean, d0z = v0.z - mean, d0w = v0.w - mean;
        float d1x = v1.x - mean, d1y = v1.y - mean, d1z = v1.z - mean, d1w = v1.w - mean;
        float var = wred(d0x * d0x + d0y * d0y + d0z * d0z + d0w * d0w +
                         d1x * d1x + d1y * d1y + d1z * d1z + d1w * d1w) * (1.f / 256.f);
        float rstd = rsqrtf(var + 1e-5f);
        if (row < NN) {
            float4 y0, y1;
            y0.x = d0x * rstd * g0.x + h0.x; y0.y = d0y * rstd * g0.y + h0.y;
            y0.z = d0z * rstd * g0.z + h0.z; y0.w = d0w * rstd * g0.w + h0.w;
            y1.x = d1x * rstd * g1.x + h1.x; y1.y = d1y * rstd * g1.y + h1.y;
            y1.z = d1z * rstd * g1.z + h1.z; y1.w = d1w * rstd * g1.w + h1.w;
            *(float4*)(n_out + (size_t)row * 256 + cb) = y0;
            *(float4*)(n_out + (size_t)row * 256 + cb + 4) = y1;
        }
    }
}

// ---------------- launch ----------------
extern "C" void kernel_launch(void* const* d_in, const int* in_sizes, int n_in,
                              void* d_out, int out_size) {
    const float* nf  = (const float*)d_in[0];
    const float* ef  = (const float*)d_in[1];
    const int*   ei  = (const int*)d_in[2];
    const float* ew1 = (const float*)d_in[3];
    const float* eb1 = (const float*)d_in[4];
    const float* ew2 = (const float*)d_in[5];
    const float* eb2 = (const float*)d_in[6];
    const float* eng = (const float*)d_in[7];
    const float* enb = (const float*)d_in[8];
    const float* aw  = (const float*)d_in[9];
    const float* ab  = (const float*)d_in[10];
    const float* evw = (const float*)d_in[11];
    const float* evb = (const float*)d_in[12];
    const float* ow1 = (const float*)d_in[13];
    const float* ob1 = (const float*)d_in[14];
    const float* ow2 = (const float*)d_in[15];
    const float* ob2 = (const float*)d_in[16];
    const float* nng = (const float*)d_in[17];
    const float* nnb = (const float*)d_in[18];

    float* out = (float*)d_out;
    float* n_out = out;                        // (N, 256)
    float* e_out = out + (size_t)NN * 256;     // (E, 128)

    const int SMEM4 = (64 * 256 + 16 * 256 + 64) * 4;
    cudaFuncSetAttribute(k1_edge_mma, cudaFuncAttributeMaxDynamicSharedMemorySize, SMEM_K1);
    cudaFuncSetAttribute(k4_node, cudaFuncAttributeMaxDynamicSharedMemorySize, SMEM4);

    k_prep<<<768, 256>>>(ew1, ew2);
    k0_node_prep<<<(NN + 7) / 8, 256>>>(nf, aw);
    k1_edge_mma<<<TILES64, 256, SMEM_K1>>>(nf, ef, ei, eb1, eb2, eng, enb, aw, ab, e_out);
    k2_exp<<<(EE + 255) / 256, 256>>>(ei);
    k3_scatter<<<EE / 2, 256>>>(ei, e_out);
    k4_node<<<(NN + 63) / 64, 256, SMEM4>>>(nf, evw, evb, ow1, ob1, ow2, ob2, nng, nnb, n_out);
}